// round 2
// baseline (speedup 1.0000x reference)
#include <cuda_runtime.h>

#define BB 64
#define TT 1024
#define EE 256
#define CIN 8
#define OUTD 63
#define NROW (BB*TT)          // 65536
#define ROWSTRIDE (BB*EE)     // 16384

// ---------------- scratch (device globals; no cudaMalloc allowed) ----------
__device__ float g_y[NROW * EE];                  // conv output / BN input  [row=(t*B+b)][e]
__device__ float g_spad[(TT + 2) * BB * EE];      // spikes, padded in time: row tp=t+1
__device__ float g_wt[3 * 3 * EE * EE];           // repacked conv weights [layer][(k*E+c)][o]
__device__ float g_w0[3 * CIN * EE];              // repacked conv0 weights [(k*8+c)][o]
__device__ float g_psum[256 * EE];                // BN partial sums
__device__ float g_psq[256 * EE];
__device__ float g_sum[EE];
__device__ float g_sq[EE];
__device__ float g_rate[BB * EE];                 // final spike rates

// ---------------- prep kernels ---------------------------------------------
__global__ void repack_wt_k(const float* __restrict__ w) {
    int idx = blockIdx.x * blockDim.x + threadIdx.x;
    if (idx >= 3 * 768 * 256) return;
    int o = idx & 255;
    int c = (idx >> 8) & 255;
    int t2 = idx >> 16;          // 0..8 == i*3+k
    int k = t2 % 3;
    int i = t2 / 3;
    g_wt[idx] = w[((i * 256 + o) * 256 + c) * 3 + k];
}

__global__ void repack_w0_k(const float* __restrict__ w0) {
    int idx = blockIdx.x * blockDim.x + threadIdx.x;
    if (idx >= 3 * CIN * 256) return;
    int o = idx & 255;
    int c = (idx >> 8) & 7;
    int k = idx >> 11;
    g_w0[idx] = w0[(o * CIN + c) * 3 + k];
}

__global__ void zero_pads_k() {
    int idx = blockIdx.x * blockDim.x + threadIdx.x;
    if (idx < ROWSTRIDE) g_spad[idx] = 0.f;
    else if (idx < 2 * ROWSTRIDE) g_spad[(TT + 1) * ROWSTRIDE + (idx - ROWSTRIDE)] = 0.f;
}

// ---------------- conv0: x[B,T,8] -> y[(t,b)][o] ----------------------------
__global__ void conv0_k(const float* __restrict__ x, const float* __restrict__ bias) {
    __shared__ float ws[24 * 256];
    __shared__ float xs[16][24];
    int t = blockIdx.x >> 2;
    int b0 = (blockIdx.x & 3) * 16;
    int tid = threadIdx.x;
#pragma unroll
    for (int j = 0; j < 24; j++) ws[j * 256 + tid] = g_w0[j * 256 + tid];
    // 384 entries, 256 threads: strided loop (R1 bug: rows 11-15 were never loaded)
    for (int q = tid; q < 384; q += 256) {
        int bl = q / 24, rem = q % 24;
        int k = rem >> 3, c = rem & 7;
        int ttm = t - 1 + k;
        float v = 0.f;
        if (ttm >= 0 && ttm < TT) v = x[((b0 + bl) * TT + ttm) * CIN + c];
        xs[bl][rem] = v;
    }
    __syncthreads();
    int o = tid;
    float bo = bias[o];
    for (int r = 0; r < 16; r++) {
        float acc = bo;
#pragma unroll
        for (int j = 0; j < 24; j++) acc += ws[j * 256 + o] * xs[r][j];
        g_y[(t * BB + b0 + r) * EE + o] = acc;
    }
}

// ---------------- conv layers 1..3 as tiled SGEMM ---------------------------
// y[M=65536, N=256] = A(spad shifted views)[M, K=768] * Wt[K, 256] + bias
__global__ void __launch_bounds__(256, 2) conv_gemm_k(int layer, const float* __restrict__ bias) {
    __shared__ float As[8][128];
    __shared__ float Bs[8][128];
    const float* __restrict__ Wt = g_wt + layer * 768 * 256;

    int mt = blockIdx.y;            // 0..511, covers t = 2*mt .. 2*mt+1
    int n0 = blockIdx.x * 128;      // 0 or 128
    int tid = threadIdx.x;

    int arow = tid >> 1;            // 0..127
    int acol = (tid & 1) << 2;      // 0 or 4
    int brow = tid >> 5;            // 0..7
    int bcol = (tid & 31) << 2;     // 0..124
    int ty = tid >> 4, tx = tid & 15;

    int ab = arow & 63;             // b
    int at = arow >> 6;             // t offset within tile (0/1)

    float acc[8][8];
#pragma unroll
    for (int i = 0; i < 8; i++)
#pragma unroll
        for (int j = 0; j < 8; j++) acc[i][j] = 0.f;

    float4 pa, pb;
    {
        int kg = acol;
        int tp = mt * 2 + at + (kg >> 8);
        pa = *(const float4*)(g_spad + tp * ROWSTRIDE + ab * EE + (kg & 255));
        int kgb = brow;
        pb = *(const float4*)(Wt + kgb * EE + n0 + bcol);
    }

    for (int ck = 0; ck < 96; ck++) {
        As[acol + 0][arow] = pa.x;
        As[acol + 1][arow] = pa.y;
        As[acol + 2][arow] = pa.z;
        As[acol + 3][arow] = pa.w;
        *(float4*)&Bs[brow][bcol] = pb;
        __syncthreads();
        if (ck < 95) {
            int kg = (ck + 1) * 8 + acol;
            int tp = mt * 2 + at + (kg >> 8);
            pa = *(const float4*)(g_spad + tp * ROWSTRIDE + ab * EE + (kg & 255));
            int kgb = (ck + 1) * 8 + brow;
            pb = *(const float4*)(Wt + kgb * EE + n0 + bcol);
        }
#pragma unroll
        for (int kk = 0; kk < 8; kk++) {
            float ar[8], br[8];
            *(float4*)(ar + 0) = *(const float4*)&As[kk][ty * 8 + 0];
            *(float4*)(ar + 4) = *(const float4*)&As[kk][ty * 8 + 4];
            *(float4*)(br + 0) = *(const float4*)&Bs[kk][tx * 8 + 0];
            *(float4*)(br + 4) = *(const float4*)&Bs[kk][tx * 8 + 4];
#pragma unroll
            for (int i = 0; i < 8; i++)
#pragma unroll
                for (int j = 0; j < 8; j++) acc[i][j] += ar[i] * br[j];
        }
        __syncthreads();
    }

    float bb[8];
#pragma unroll
    for (int j = 0; j < 8; j++) bb[j] = bias[n0 + tx * 8 + j];
#pragma unroll
    for (int i = 0; i < 8; i++) {
        int row = mt * 128 + ty * 8 + i;
        float* yo = g_y + row * EE + n0 + tx * 8;
        float4 v0, v1;
        v0.x = acc[i][0] + bb[0]; v0.y = acc[i][1] + bb[1];
        v0.z = acc[i][2] + bb[2]; v0.w = acc[i][3] + bb[3];
        v1.x = acc[i][4] + bb[4]; v1.y = acc[i][5] + bb[5];
        v1.z = acc[i][6] + bb[6]; v1.w = acc[i][7] + bb[7];
        *(float4*)(yo + 0) = v0;
        *(float4*)(yo + 4) = v1;
    }
}

// ---------------- BN batch statistics (deterministic 2-stage) ---------------
__global__ void stats1_k() {
    int e = threadIdx.x;
    int blk = blockIdx.x;
    const float* yp = g_y + (blk * 256) * EE + e;
    float s = 0.f, q = 0.f;
#pragma unroll 4
    for (int r = 0; r < 256; r++) {
        float v = yp[r * EE];
        s += v;
        q += v * v;
    }
    g_psum[blk * EE + e] = s;
    g_psq[blk * EE + e] = q;
}

__global__ void stats2_k() {
    int e = threadIdx.x;
    float s = 0.f, q = 0.f;
#pragma unroll 4
    for (int blk = 0; blk < 256; blk++) {
        s += g_psum[blk * EE + e];
        q += g_psq[blk * EE + e];
    }
    g_sum[e] = s;
    g_sq[e] = q;
}

// ---------------- BN apply + LIF scan over T --------------------------------
__global__ void lif_k(const float* __restrict__ gamma, const float* __restrict__ beta,
                      int write_rate) {
    int e = threadIdx.x;
    int b = blockIdx.x;
    float mu = g_sum[e] * (1.f / NROW);
    float var = g_sq[e] * (1.f / NROW) - mu * mu;
    float sc = gamma[e] / sqrtf(var + 1e-5f);
    float sh = fmaf(-mu, sc, beta[e]);

    const float* yp = g_y + b * EE + e;
    float* sp = g_spad + ROWSTRIDE + b * EE + e;   // tp = t+1
    float v = 0.f, cnt = 0.f;
    float nxt = yp[0];
#pragma unroll 4
    for (int t = 0; t < TT; t++) {
        float xv = nxt;
        if (t + 1 < TT) nxt = yp[(t + 1) * ROWSTRIDE];
        float yn = fmaf(xv, sc, sh);
        v = 0.5f * (v + yn);
        float s = (v >= 1.f) ? 1.f : 0.f;
        sp[t * ROWSTRIDE] = s;
        cnt += s;
        v = (v >= 1.f) ? 0.f : v;
    }
    if (write_rate) g_rate[b * EE + e] = cnt * (1.f / TT);
}

// ---------------- head ------------------------------------------------------
__global__ void head_k(const float* __restrict__ hw, const float* __restrict__ hb,
                       float* __restrict__ out) {
    __shared__ float rs[EE];
    int b = blockIdx.x, tid = threadIdx.x;   // 64 threads
    for (int j = tid; j < EE; j += 64) rs[j] = g_rate[b * EE + j];
    __syncthreads();
    if (tid < OUTD) {
        float acc = hb[tid];
#pragma unroll 8
        for (int e2 = 0; e2 < EE; e2++) acc += rs[e2] * hw[tid * EE + e2];
        out[b * OUTD + tid] = acc;
    }
}

// ---------------- launch ----------------------------------------------------
extern "C" void kernel_launch(void* const* d_in, const int* in_sizes, int n_in,
                              void* d_out, int out_size) {
    // Resolve inputs by element count (robust to metadata ordering).
    const float *x = 0, *conv0_w = 0, *conv0_b = 0, *convs_w = 0, *convs_b = 0;
    const float *gamma = 0, *beta = 0, *head_w = 0, *head_b = 0;
    int n1024_seen = 0;
    // If inputs are alphabetical, bn_beta precedes bn_gamma; detect by first size.
    int alphabetical = (n_in > 0 && in_sizes[0] == 1024);
    for (int i = 0; i < n_in; i++) {
        const float* p = (const float*)d_in[i];
        switch (in_sizes[i]) {
            case 524288: x = p; break;
            case 6144:   conv0_w = p; break;
            case 256:    conv0_b = p; break;
            case 589824: convs_w = p; break;
            case 768:    convs_b = p; break;
            case 16128:  head_w = p; break;
            case 63:     head_b = p; break;
            case 1024:
                if (n1024_seen == 0) { if (alphabetical) beta = p; else gamma = p; }
                else                 { if (alphabetical) gamma = p; else beta = p; }
                n1024_seen++;
                break;
            default: break;
        }
    }
    float* out = (float*)d_out;

    repack_wt_k<<<(3 * 768 * 256 + 255) / 256, 256>>>(convs_w);
    repack_w0_k<<<(3 * CIN * 256 + 255) / 256, 256>>>(conv0_w);
    zero_pads_k<<<(2 * ROWSTRIDE + 255) / 256, 256>>>();

    // block 0
    conv0_k<<<TT * 4, 256>>>(x, conv0_b);
    stats1_k<<<256, 256>>>();
    stats2_k<<<1, 256>>>();
    lif_k<<<BB, 256>>>(gamma + 0 * EE, beta + 0 * EE, 0);

    // blocks 1..3
    for (int i = 0; i < 3; i++) {
        conv_gemm_k<<<dim3(2, 512), 256>>>(i, convs_b + i * EE);
        stats1_k<<<256, 256>>>();
        stats2_k<<<1, 256>>>();
        lif_k<<<BB, 256>>>(gamma + (i + 1) * EE, beta + (i + 1) * EE, (i == 2) ? 1 : 0);
    }

    head_k<<<BB, 64>>>(head_w, head_b, out);
}

// round 6
// speedup vs baseline: 3.3469x; 3.3469x over previous
#include <cuda_runtime.h>
#include <cuda_bf16.h>
#include <cstdint>

#define BB 64
#define TT 1024
#define EE 256
#define CIN 8
#define OUTD 63
#define NROW (BB*TT)          // 65536
#define ROWSTRIDE (BB*EE)     // 16384

typedef __nv_bfloat16 bf16;

// ---------------- scratch ----------------------------------------------------
__device__ float g_y[NROW * EE];                              // conv out [(t*B+b)][e]
__device__ __align__(16) bf16 g_spad[(TT + 2) * ROWSTRIDE];   // bf16 spikes, t-padded
__device__ __align__(16) bf16 g_wbf[3 * 3 * 768 * 256];       // bf16 weights [layer][split][k][n]
__device__ float g_w0[3 * CIN * EE];
__device__ float g_psum[256 * EE];
__device__ float g_psq[256 * EE];
__device__ float g_sum[EE];
__device__ float g_sq[EE];
__device__ float g_rate[BB * EE];

// ---------------- ptx helpers ------------------------------------------------
__device__ __forceinline__ uint32_t smem_u32(const void* p) {
    uint32_t a;
    asm("{ .reg .u64 t; cvta.to.shared.u64 t, %1; cvt.u32.u64 %0, t; }" : "=r"(a) : "l"(p));
    return a;
}
__device__ __forceinline__ void ldm4(uint32_t* r, uint32_t a) {
    asm volatile("ldmatrix.sync.aligned.m8n8.x4.shared.b16 {%0,%1,%2,%3}, [%4];"
                 : "=r"(r[0]), "=r"(r[1]), "=r"(r[2]), "=r"(r[3]) : "r"(a));
}
__device__ __forceinline__ void ldm4t(uint32_t* r, uint32_t a) {
    asm volatile("ldmatrix.sync.aligned.m8n8.x4.trans.shared.b16 {%0,%1,%2,%3}, [%4];"
                 : "=r"(r[0]), "=r"(r[1]), "=r"(r[2]), "=r"(r[3]) : "r"(a));
}
__device__ __forceinline__ void mma_bf(float* d, const uint32_t* a, const uint32_t* b) {
    asm volatile("mma.sync.aligned.m16n8k16.row.col.f32.bf16.bf16.f32 "
                 "{%0,%1,%2,%3}, {%4,%5,%6,%7}, {%8,%9}, {%0,%1,%2,%3};"
                 : "+f"(d[0]), "+f"(d[1]), "+f"(d[2]), "+f"(d[3])
                 : "r"(a[0]), "r"(a[1]), "r"(a[2]), "r"(a[3]), "r"(b[0]), "r"(b[1]));
}

// ---------------- prep kernels -----------------------------------------------
__global__ void repack_wbf_k(const float* __restrict__ w) {
    int idx = blockIdx.x * blockDim.x + threadIdx.x;     // 3*768*256
    if (idx >= 3 * 768 * 256) return;
    int n = idx & 255;
    int k = (idx >> 8) % 768;          // k = kpos*256 + c
    int i = idx / (768 * 256);
    int kpos = k >> 8;
    int c = k & 255;
    float wf = w[((i * 256 + n) * 256 + c) * 3 + kpos];
    bf16 b0 = __float2bfloat16_rn(wf);
    float r1 = wf - __bfloat162float(b0);
    bf16 b1 = __float2bfloat16_rn(r1);
    float r2 = r1 - __bfloat162float(b1);
    bf16 b2 = __float2bfloat16_rn(r2);
    g_wbf[((size_t)(i * 3 + 0) * 768 + k) * 256 + n] = b0;
    g_wbf[((size_t)(i * 3 + 1) * 768 + k) * 256 + n] = b1;
    g_wbf[((size_t)(i * 3 + 2) * 768 + k) * 256 + n] = b2;
}

__global__ void repack_w0_k(const float* __restrict__ w0) {
    int idx = blockIdx.x * blockDim.x + threadIdx.x;
    if (idx >= 3 * CIN * 256) return;
    int o = idx & 255;
    int c = (idx >> 8) & 7;
    int k = idx >> 11;
    g_w0[idx] = w0[(o * CIN + c) * 3 + k];
}

__global__ void zero_pads_k() {
    int idx = blockIdx.x * blockDim.x + threadIdx.x;
    if (idx < ROWSTRIDE) g_spad[idx] = __float2bfloat16(0.f);
    else if (idx < 2 * ROWSTRIDE) g_spad[(TT + 1) * ROWSTRIDE + (idx - ROWSTRIDE)] = __float2bfloat16(0.f);
}

// ---------------- conv0 (fp32, small K) ---------------------------------------
__global__ void conv0_k(const float* __restrict__ x, const float* __restrict__ bias) {
    __shared__ float ws[24 * 256];
    __shared__ float xs[16][24];
    int t = blockIdx.x >> 2;
    int b0 = (blockIdx.x & 3) * 16;
    int tid = threadIdx.x;
#pragma unroll
    for (int j = 0; j < 24; j++) ws[j * 256 + tid] = g_w0[j * 256 + tid];
    for (int q = tid; q < 384; q += 256) {
        int bl = q / 24, rem = q % 24;
        int k = rem >> 3, c = rem & 7;
        int ttm = t - 1 + k;
        float v = 0.f;
        if (ttm >= 0 && ttm < TT) v = x[((b0 + bl) * TT + ttm) * CIN + c];
        xs[bl][rem] = v;
    }
    __syncthreads();
    int o = tid;
    float bo = bias[o];
    for (int r = 0; r < 16; r++) {
        float acc = bo;
#pragma unroll
        for (int j = 0; j < 24; j++) acc += ws[j * 256 + o] * xs[r][j];
        g_y[(size_t)(t * BB + b0 + r) * EE + o] = acc;
    }
}

// ---------------- bf16 MMA conv GEMM --------------------------------------------
// y[128m x 128n] per CTA; K = 768 channels x 3 bf16 splits, chunks of 32.
// smem: A [2 stages][128][40], B [2 stages][3 splits][32][136] (bf16 halves)
#define APITCH 40
#define BPITCH 136
#define A_ST 5120              // halves per A stage
#define B_OFF 10240            // halves offset of B region
#define B_SP 4352              // halves per (stage,split) B tile: 32*136
#define B_STAGE (3 * B_SP)
#define SMEM_HALVES (B_OFF + 2 * B_STAGE)
#define SMEM_BYTES (SMEM_HALVES * 2)

__global__ void __launch_bounds__(256, 1) conv_mma_k(int layer, const float* __restrict__ bias) {
    extern __shared__ bf16 sm[];
    const int tid = threadIdx.x;
    const int lane = tid & 31;
    const int wid = tid >> 5;
    const int wm = wid & 3;          // warp M (32 rows)
    const int wn = wid >> 2;         // warp N (64 cols)
    const int mt = blockIdx.y;       // 512 M tiles
    const int nb = blockIdx.x;       // 2 N tiles

    const uint4* __restrict__ wsrc = (const uint4*)(g_wbf + (size_t)layer * 3 * 768 * 256);

    float acc[2][8][4];
#pragma unroll
    for (int mi = 0; mi < 2; mi++)
#pragma unroll
        for (int ni = 0; ni < 8; ni++)
#pragma unroll
            for (int q = 0; q < 4; q++) acc[mi][ni][q] = 0.f;

    const int ar0 = tid >> 2;            // A row (plus it*64)
    const int aq = tid & 3;              // 16B quarter within 64B row
    // prefetch chunk 0
    uint4 pa[2], pb[6];
    {
        const int kpos = 0, c0 = 0;
#pragma unroll
        for (int it = 0; it < 2; it++) {
            int row = ar0 + it * 64;
            pa[it] = *(const uint4*)(g_spad + (size_t)(2 * mt + (row >> 6) + kpos) * ROWSTRIDE
                                     + (row & 63) * 256 + c0 + aq * 8);
        }
#pragma unroll
        for (int it = 0; it < 6; it++) {
            int u = tid + it * 256;
            int s = u >> 9, rest = u & 511;
            int kk = rest >> 4, g = rest & 15;
            pb[it] = wsrc[(size_t)(s * 768 + kpos * 256 + c0 + kk) * 32 + nb * 16 + g];
        }
    }
    // store chunk 0 into stage 0
#pragma unroll
    for (int it = 0; it < 2; it++) {
        int row = ar0 + it * 64;
        *(uint4*)(sm + row * APITCH + aq * 8) = pa[it];
    }
#pragma unroll
    for (int it = 0; it < 6; it++) {
        int u = tid + it * 256;
        int s = u >> 9, rest = u & 511;
        int kk = rest >> 4, g = rest & 15;
        *(uint4*)(sm + B_OFF + s * B_SP + kk * BPITCH + g * 8) = pb[it];
    }
    __syncthreads();

    for (int ck = 0; ck < 24; ck++) {
        const int st = ck & 1;
        if (ck < 23) {
            int ck1 = ck + 1;
            int kpos = ck1 >> 3, c0 = (ck1 & 7) << 5;
#pragma unroll
            for (int it = 0; it < 2; it++) {
                int row = ar0 + it * 64;
                pa[it] = *(const uint4*)(g_spad + (size_t)(2 * mt + (row >> 6) + kpos) * ROWSTRIDE
                                         + (row & 63) * 256 + c0 + aq * 8);
            }
#pragma unroll
            for (int it = 0; it < 6; it++) {
                int u = tid + it * 256;
                int s = u >> 9, rest = u & 511;
                int kk = rest >> 4, g = rest & 15;
                pb[it] = wsrc[(size_t)(s * 768 + kpos * 256 + c0 + kk) * 32 + nb * 16 + g];
            }
        }
        // compute on stage st
        const bf16* Asm = sm + st * A_ST;
        const bf16* Bsm = sm + B_OFF + st * B_STAGE;
#pragma unroll
        for (int kh = 0; kh < 2; kh++) {
            uint32_t afr[2][4];
#pragma unroll
            for (int mi = 0; mi < 2; mi++) {
                uint32_t ad = smem_u32(Asm + (wm * 32 + mi * 16 + (lane & 15)) * APITCH
                                       + kh * 16 + (lane >> 4) * 8);
                ldm4(afr[mi], ad);
            }
#pragma unroll
            for (int s = 0; s < 3; s++) {
                uint32_t bfr[4][4];
#pragma unroll
                for (int q = 0; q < 4; q++) {
                    uint32_t bd = smem_u32(Bsm + s * B_SP + (kh * 16 + (lane & 15)) * BPITCH
                                           + wn * 64 + q * 16 + (lane >> 4) * 8);
                    ldm4t(bfr[q], bd);
                }
#pragma unroll
                for (int mi = 0; mi < 2; mi++)
#pragma unroll
                    for (int ni = 0; ni < 8; ni++)
                        mma_bf(acc[mi][ni], afr[mi], &bfr[ni >> 1][(ni & 1) * 2]);
            }
        }
        if (ck < 23) {
            __syncthreads();
            const int st1 = st ^ 1;
#pragma unroll
            for (int it = 0; it < 2; it++) {
                int row = ar0 + it * 64;
                *(uint4*)(sm + st1 * A_ST + row * APITCH + aq * 8) = pa[it];
            }
#pragma unroll
            for (int it = 0; it < 6; it++) {
                int u = tid + it * 256;
                int s = u >> 9, rest = u & 511;
                int kk = rest >> 4, g = rest & 15;
                *(uint4*)(sm + B_OFF + st1 * B_STAGE + s * B_SP + kk * BPITCH + g * 8) = pb[it];
            }
            __syncthreads();
        }
    }

    // epilogue
    const int m0 = mt * 128 + wm * 32 + (lane >> 2);
    const int nc0 = nb * 128 + wn * 64 + (lane & 3) * 2;
#pragma unroll
    for (int ni = 0; ni < 8; ni++) {
        int n = nc0 + ni * 8;
        float2 bv = *(const float2*)(bias + n);
#pragma unroll
        for (int mi = 0; mi < 2; mi++) {
            int r0 = m0 + mi * 16;
            float2 v0, v1;
            v0.x = acc[mi][ni][0] + bv.x; v0.y = acc[mi][ni][1] + bv.y;
            v1.x = acc[mi][ni][2] + bv.x; v1.y = acc[mi][ni][3] + bv.y;
            *(float2*)(g_y + (size_t)r0 * 256 + n) = v0;
            *(float2*)(g_y + (size_t)(r0 + 8) * 256 + n) = v1;
        }
    }
}

// ---------------- BN stats (deterministic 2-stage) -----------------------------
__global__ void stats1_k() {
    int e = threadIdx.x;
    int blk = blockIdx.x;
    const float* yp = g_y + (size_t)(blk * 256) * EE + e;
    float s = 0.f, q = 0.f;
#pragma unroll 4
    for (int r = 0; r < 256; r++) {
        float v = yp[(size_t)r * EE];
        s += v;
        q += v * v;
    }
    g_psum[blk * EE + e] = s;
    g_psq[blk * EE + e] = q;
}

__global__ void stats2_k() {
    int e = threadIdx.x;
    float s = 0.f, q = 0.f;
#pragma unroll 4
    for (int blk = 0; blk < 256; blk++) {
        s += g_psum[blk * EE + e];
        q += g_psq[blk * EE + e];
    }
    g_sum[e] = s;
    g_sq[e] = q;
}

// ---------------- BN apply + LIF (prefetch depth 8) ----------------------------
__global__ void lif_k(const float* __restrict__ gamma, const float* __restrict__ beta,
                      int write_rate) {
    int b = blockIdx.x >> 2;
    int e = ((blockIdx.x & 3) << 6) + threadIdx.x;   // blockDim = 64
    float mu = g_sum[e] * (1.f / NROW);
    float var = g_sq[e] * (1.f / NROW) - mu * mu;
    float sc = gamma[e] / sqrtf(var + 1e-5f);
    float sh = fmaf(-mu, sc, beta[e]);

    const float* yp = g_y + b * 256 + e;
    bf16* sp = g_spad + ROWSTRIDE + b * 256 + e;

    float buf[8];
#pragma unroll
    for (int i = 0; i < 8; i++) buf[i] = yp[(size_t)i * ROWSTRIDE];
    float v = 0.f, cnt = 0.f;
#pragma unroll 8
    for (int t = 0; t < TT; t++) {
        float xv = buf[t & 7];
        if (t + 8 < TT) buf[t & 7] = yp[(size_t)(t + 8) * ROWSTRIDE];
        float yn = fmaf(xv, sc, sh);
        v = 0.5f * (v + yn);
        float s = (v >= 1.f) ? 1.f : 0.f;
        sp[(size_t)t * ROWSTRIDE] = __float2bfloat16(s);
        cnt += s;
        v = (v >= 1.f) ? 0.f : v;
    }
    if (write_rate) g_rate[b * 256 + e] = cnt * (1.f / TT);
}

// ---------------- head ----------------------------------------------------------
__global__ void head_k(const float* __restrict__ hw, const float* __restrict__ hb,
                       float* __restrict__ out) {
    __shared__ float rs[EE];
    int b = blockIdx.x, tid = threadIdx.x;   // 64 threads
    for (int j = tid; j < EE; j += 64) rs[j] = g_rate[b * EE + j];
    __syncthreads();
    if (tid < OUTD) {
        float acc = hb[tid];
#pragma unroll 8
        for (int e2 = 0; e2 < EE; e2++) acc += rs[e2] * hw[tid * EE + e2];
        out[b * OUTD + tid] = acc;
    }
}

// ---------------- launch ---------------------------------------------------------
extern "C" void kernel_launch(void* const* d_in, const int* in_sizes, int n_in,
                              void* d_out, int out_size) {
    const float *x = 0, *conv0_w = 0, *conv0_b = 0, *convs_w = 0, *convs_b = 0;
    const float *gamma = 0, *beta = 0, *head_w = 0, *head_b = 0;
    int n1024_seen = 0;
    int alphabetical = (n_in > 0 && in_sizes[0] == 1024);
    for (int i = 0; i < n_in; i++) {
        const float* p = (const float*)d_in[i];
        switch (in_sizes[i]) {
            case 524288: x = p; break;
            case 6144:   conv0_w = p; break;
            case 256:    conv0_b = p; break;
            case 589824: convs_w = p; break;
            case 768:    convs_b = p; break;
            case 16128:  head_w = p; break;
            case 63:     head_b = p; break;
            case 1024:
                if (n1024_seen == 0) { if (alphabetical) beta = p; else gamma = p; }
                else                 { if (alphabetical) gamma = p; else beta = p; }
                n1024_seen++;
                break;
            default: break;
        }
    }
    float* out = (float*)d_out;

    cudaFuncSetAttribute(conv_mma_k, cudaFuncAttributeMaxDynamicSharedMemorySize, SMEM_BYTES);

    repack_wbf_k<<<(3 * 768 * 256 + 255) / 256, 256>>>(convs_w);
    repack_w0_k<<<(3 * CIN * 256 + 255) / 256, 256>>>(conv0_w);
    zero_pads_k<<<(2 * ROWSTRIDE + 255) / 256, 256>>>();

    // block 0
    conv0_k<<<TT * 4, 256>>>(x, conv0_b);
    stats1_k<<<256, 256>>>();
    stats2_k<<<1, 256>>>();
    lif_k<<<BB * 4, 64>>>(gamma + 0 * EE, beta + 0 * EE, 0);

    // blocks 1..3 (bf16 tensor-core GEMM, 3-way exact split)
    for (int i = 0; i < 3; i++) {
        conv_mma_k<<<dim3(2, 512), 256, SMEM_BYTES>>>(i, convs_b + i * EE);
        stats1_k<<<256, 256>>>();
        stats2_k<<<1, 256>>>();
        lif_k<<<BB * 4, 64>>>(gamma + (i + 1) * EE, beta + (i + 1) * EE, (i == 2) ? 1 : 0);
    }

    head_k<<<BB, 64>>>(head_w, head_b, out);
}

// round 7
// speedup vs baseline: 3.5833x; 1.0706x over previous
#include <cuda_runtime.h>
#include <cuda_fp16.h>
#include <cstdint>

#define BB 64
#define TT 1024
#define EE 256
#define CIN 8
#define OUTD 63
#define NROW (BB*TT)          // 65536
#define ROWSTRIDE (BB*EE)     // 16384

#define LO_SCALE 4096.f
#define LO_INV   (1.f/4096.f)

// ---------------- scratch ----------------------------------------------------
__device__ float g_y[NROW * EE];                                // conv out [(t*B+b)][e]
__device__ __align__(16) __half g_spad[(TT + 2) * ROWSTRIDE];   // fp16 spikes, t-padded
__device__ __align__(16) __half g_wh[3 * 2 * 768 * 256];        // fp16 weights [layer][split][k][n]
__device__ float g_w0[3 * CIN * EE];
__device__ float g_psum[512 * EE];
__device__ float g_psq[512 * EE];
__device__ float g_sum[EE];
__device__ float g_sq[EE];
__device__ float g_rate[BB * EE];

// ---------------- ptx helpers ------------------------------------------------
__device__ __forceinline__ uint32_t smem_u32(const void* p) {
    uint32_t a;
    asm("{ .reg .u64 t; cvta.to.shared.u64 t, %1; cvt.u32.u64 %0, t; }" : "=r"(a) : "l"(p));
    return a;
}
__device__ __forceinline__ void ldm4(uint32_t* r, uint32_t a) {
    asm volatile("ldmatrix.sync.aligned.m8n8.x4.shared.b16 {%0,%1,%2,%3}, [%4];"
                 : "=r"(r[0]), "=r"(r[1]), "=r"(r[2]), "=r"(r[3]) : "r"(a));
}
__device__ __forceinline__ void ldm4t(uint32_t* r, uint32_t a) {
    asm volatile("ldmatrix.sync.aligned.m8n8.x4.trans.shared.b16 {%0,%1,%2,%3}, [%4];"
                 : "=r"(r[0]), "=r"(r[1]), "=r"(r[2]), "=r"(r[3]) : "r"(a));
}
__device__ __forceinline__ void mma_h(float* d, const uint32_t* a, const uint32_t* b) {
    asm volatile("mma.sync.aligned.m16n8k16.row.col.f32.f16.f16.f32 "
                 "{%0,%1,%2,%3}, {%4,%5,%6,%7}, {%8,%9}, {%0,%1,%2,%3};"
                 : "+f"(d[0]), "+f"(d[1]), "+f"(d[2]), "+f"(d[3])
                 : "r"(a[0]), "r"(a[1]), "r"(a[2]), "r"(a[3]), "r"(b[0]), "r"(b[1]));
}

// ---------------- prep kernels -----------------------------------------------
__global__ void repack_wh_k(const float* __restrict__ w) {
    int idx = blockIdx.x * blockDim.x + threadIdx.x;     // 3*768*256
    if (idx >= 3 * 768 * 256) return;
    int n = idx & 255;
    int k = (idx >> 8) % 768;          // k = kpos*256 + c
    int i = idx / (768 * 256);
    int kpos = k >> 8;
    int c = k & 255;
    float wf = w[((i * 256 + n) * 256 + c) * 3 + kpos];
    __half h0 = __float2half_rn(wf);
    float lo = (wf - __half2float(h0)) * LO_SCALE;       // residual lifted to normal range
    __half h1 = __float2half_rn(lo);
    g_wh[((size_t)(i * 2 + 0) * 768 + k) * 256 + n] = h0;
    g_wh[((size_t)(i * 2 + 1) * 768 + k) * 256 + n] = h1;
}

__global__ void repack_w0_k(const float* __restrict__ w0) {
    int idx = blockIdx.x * blockDim.x + threadIdx.x;
    if (idx >= 3 * CIN * 256) return;
    int o = idx & 255;
    int c = (idx >> 8) & 7;
    int k = idx >> 11;
    g_w0[idx] = w0[(o * CIN + c) * 3 + k];
}

__global__ void zero_pads_k() {
    int idx = blockIdx.x * blockDim.x + threadIdx.x;
    if (idx < ROWSTRIDE) g_spad[idx] = __float2half(0.f);
    else if (idx < 2 * ROWSTRIDE) g_spad[(TT + 1) * ROWSTRIDE + (idx - ROWSTRIDE)] = __float2half(0.f);
}

// ---------------- conv0 (fp32, small K) ---------------------------------------
__global__ void conv0_k(const float* __restrict__ x, const float* __restrict__ bias) {
    __shared__ float ws[24 * 256];
    __shared__ float xs[16][24];
    int t = blockIdx.x >> 2;
    int b0 = (blockIdx.x & 3) * 16;
    int tid = threadIdx.x;
#pragma unroll
    for (int j = 0; j < 24; j++) ws[j * 256 + tid] = g_w0[j * 256 + tid];
    for (int q = tid; q < 384; q += 256) {
        int bl = q / 24, rem = q % 24;
        int k = rem >> 3, c = rem & 7;
        int ttm = t - 1 + k;
        float v = 0.f;
        if (ttm >= 0 && ttm < TT) v = x[((b0 + bl) * TT + ttm) * CIN + c];
        xs[bl][rem] = v;
    }
    __syncthreads();
    int o = tid;
    float bo = bias[o];
    for (int r = 0; r < 16; r++) {
        float acc = bo;
#pragma unroll
        for (int j = 0; j < 24; j++) acc += ws[j * 256 + o] * xs[r][j];
        g_y[(size_t)(t * BB + b0 + r) * EE + o] = acc;
    }
}

// ---------------- fp16 scaled-2-split MMA conv GEMM + fused stats ----------------
// y[128m x 128n] per CTA; K = 768 channels x 2 fp16 splits, chunks of 32.
// smem: A [2 stages][128][40], B [2 stages][2 splits][32][136] halves
#define APITCH 40
#define BPITCH 136
#define A_ST 5120              // halves per A stage
#define B_OFF 10240            // halves offset of B region
#define B_SP 4352              // halves per (stage,split) B tile: 32*136
#define B_STAGE (2 * B_SP)
#define SMEM_HALVES (B_OFF + 2 * B_STAGE)   // 27648
#define SMEM_BYTES (SMEM_HALVES * 2)        // 55296

__global__ void __launch_bounds__(256, 1) conv_mma_k(int layer, const float* __restrict__ bias) {
    extern __shared__ __half sm[];
    const int tid = threadIdx.x;
    const int lane = tid & 31;
    const int wid = tid >> 5;
    const int wm = wid & 3;          // warp M (32 rows)
    const int wn = wid >> 2;         // warp N (64 cols)
    const int mt = blockIdx.y;       // 512 M tiles
    const int nb = blockIdx.x;       // 2 N tiles

    const uint4* __restrict__ wsrc = (const uint4*)(g_wh + (size_t)layer * 2 * 768 * 256);

    float acch[2][8][4], accl[2][8][4];
#pragma unroll
    for (int mi = 0; mi < 2; mi++)
#pragma unroll
        for (int ni = 0; ni < 8; ni++)
#pragma unroll
            for (int q = 0; q < 4; q++) { acch[mi][ni][q] = 0.f; accl[mi][ni][q] = 0.f; }

    const int ar0 = tid >> 2;            // A row (plus it*64)
    const int aq = tid & 3;              // 16B quarter within 64B row
    // prefetch chunk 0
    uint4 pa[2], pb[4];
    {
        const int kpos = 0, c0 = 0;
#pragma unroll
        for (int it = 0; it < 2; it++) {
            int row = ar0 + it * 64;
            pa[it] = *(const uint4*)(g_spad + (size_t)(2 * mt + (row >> 6) + kpos) * ROWSTRIDE
                                     + (row & 63) * 256 + c0 + aq * 8);
        }
#pragma unroll
        for (int it = 0; it < 4; it++) {
            int u = tid + it * 256;
            int s = u >> 9, rest = u & 511;
            int kk = rest >> 4, g = rest & 15;
            pb[it] = wsrc[(size_t)(s * 768 + kpos * 256 + c0 + kk) * 32 + nb * 16 + g];
        }
    }
    // store chunk 0 into stage 0
#pragma unroll
    for (int it = 0; it < 2; it++) {
        int row = ar0 + it * 64;
        *(uint4*)(sm + row * APITCH + aq * 8) = pa[it];
    }
#pragma unroll
    for (int it = 0; it < 4; it++) {
        int u = tid + it * 256;
        int s = u >> 9, rest = u & 511;
        int kk = rest >> 4, g = rest & 15;
        *(uint4*)(sm + B_OFF + s * B_SP + kk * BPITCH + g * 8) = pb[it];
    }
    __syncthreads();

    for (int ck = 0; ck < 24; ck++) {
        const int st = ck & 1;
        if (ck < 23) {
            int ck1 = ck + 1;
            int kpos = ck1 >> 3, c0 = (ck1 & 7) << 5;
#pragma unroll
            for (int it = 0; it < 2; it++) {
                int row = ar0 + it * 64;
                pa[it] = *(const uint4*)(g_spad + (size_t)(2 * mt + (row >> 6) + kpos) * ROWSTRIDE
                                         + (row & 63) * 256 + c0 + aq * 8);
            }
#pragma unroll
            for (int it = 0; it < 4; it++) {
                int u = tid + it * 256;
                int s = u >> 9, rest = u & 511;
                int kk = rest >> 4, g = rest & 15;
                pb[it] = wsrc[(size_t)(s * 768 + kpos * 256 + c0 + kk) * 32 + nb * 16 + g];
            }
        }
        // compute on stage st
        const __half* Asm = sm + st * A_ST;
        const __half* Bsm = sm + B_OFF + st * B_STAGE;
#pragma unroll
        for (int kh = 0; kh < 2; kh++) {
            uint32_t afr[2][4];
#pragma unroll
            for (int mi = 0; mi < 2; mi++) {
                uint32_t ad = smem_u32(Asm + (wm * 32 + mi * 16 + (lane & 15)) * APITCH
                                       + kh * 16 + (lane >> 4) * 8);
                ldm4(afr[mi], ad);
            }
#pragma unroll
            for (int s = 0; s < 2; s++) {
                uint32_t bfr[4][4];
#pragma unroll
                for (int q = 0; q < 4; q++) {
                    uint32_t bd = smem_u32(Bsm + s * B_SP + (kh * 16 + (lane & 15)) * BPITCH
                                           + wn * 64 + q * 16 + (lane >> 4) * 8);
                    ldm4t(bfr[q], bd);
                }
                if (s == 0) {
#pragma unroll
                    for (int mi = 0; mi < 2; mi++)
#pragma unroll
                        for (int ni = 0; ni < 8; ni++)
                            mma_h(acch[mi][ni], afr[mi], &bfr[ni >> 1][(ni & 1) * 2]);
                } else {
#pragma unroll
                    for (int mi = 0; mi < 2; mi++)
#pragma unroll
                        for (int ni = 0; ni < 8; ni++)
                            mma_h(accl[mi][ni], afr[mi], &bfr[ni >> 1][(ni & 1) * 2]);
                }
            }
        }
        if (ck < 23) {
            __syncthreads();
            const int st1 = st ^ 1;
#pragma unroll
            for (int it = 0; it < 2; it++) {
                int row = ar0 + it * 64;
                *(uint4*)(sm + st1 * A_ST + row * APITCH + aq * 8) = pa[it];
            }
#pragma unroll
            for (int it = 0; it < 4; it++) {
                int u = tid + it * 256;
                int s = u >> 9, rest = u & 511;
                int kk = rest >> 4, g = rest & 15;
                *(uint4*)(sm + B_OFF + st1 * B_STAGE + s * B_SP + kk * BPITCH + g * 8) = pb[it];
            }
            __syncthreads();
        }
    }

    // ---------------- epilogue: combine splits, write y, fused column stats ------
    __syncthreads();                        // smem free for reuse as reduction buffer
    float* red = (float*)sm;                // [0..512) sum: [wm][128 col]; [512..1024) sq

    const int m0 = mt * 128 + wm * 32 + (lane >> 2);
    const int nc0 = nb * 128 + wn * 64 + (lane & 3) * 2;
    float csum[16], csq[16];
#pragma unroll
    for (int j = 0; j < 16; j++) { csum[j] = 0.f; csq[j] = 0.f; }

#pragma unroll
    for (int ni = 0; ni < 8; ni++) {
        int n = nc0 + ni * 8;
        float2 bv = *(const float2*)(bias + n);
#pragma unroll
        for (int mi = 0; mi < 2; mi++) {
            int r0 = m0 + mi * 16;
            float v00 = fmaf(accl[mi][ni][0], LO_INV, acch[mi][ni][0]) + bv.x;
            float v01 = fmaf(accl[mi][ni][1], LO_INV, acch[mi][ni][1]) + bv.y;
            float v10 = fmaf(accl[mi][ni][2], LO_INV, acch[mi][ni][2]) + bv.x;
            float v11 = fmaf(accl[mi][ni][3], LO_INV, acch[mi][ni][3]) + bv.y;
            float2 w0, w1;
            w0.x = v00; w0.y = v01;
            w1.x = v10; w1.y = v11;
            *(float2*)(g_y + (size_t)r0 * 256 + n) = w0;
            *(float2*)(g_y + (size_t)(r0 + 8) * 256 + n) = w1;
            csum[ni * 2 + 0] += v00 + v10;
            csum[ni * 2 + 1] += v01 + v11;
            csq[ni * 2 + 0] += v00 * v00 + v10 * v10;
            csq[ni * 2 + 1] += v01 * v01 + v11 * v11;
        }
    }
    // reduce over the 8 row-groups within the warp (lanes sharing lane&3)
#pragma unroll
    for (int off = 4; off < 32; off <<= 1)
#pragma unroll
        for (int j = 0; j < 16; j++) {
            csum[j] += __shfl_xor_sync(0xffffffffu, csum[j], off);
            csq[j]  += __shfl_xor_sync(0xffffffffu, csq[j],  off);
        }
    if (lane < 4) {
#pragma unroll
        for (int j = 0; j < 16; j++) {
            int cl = wn * 64 + (j >> 1) * 8 + lane * 2 + (j & 1);   // 0..127 within CTA
            red[wm * 128 + cl] = csum[j];
            red[512 + wm * 128 + cl] = csq[j];
        }
    }
    __syncthreads();
    if (tid < 128) {
        float s = red[tid] + red[128 + tid] + red[256 + tid] + red[384 + tid];
        float q = red[512 + tid] + red[640 + tid] + red[768 + tid] + red[896 + tid];
        g_psum[mt * 256 + nb * 128 + tid] = s;
        g_psq[mt * 256 + nb * 128 + tid] = q;
    }
}

// ---------------- BN stats (layer 0 path + shared finalize) --------------------
__global__ void stats1_k() {
    int e = threadIdx.x;
    int blk = blockIdx.x;
    const float* yp = g_y + (size_t)(blk * 256) * EE + e;
    float s = 0.f, q = 0.f;
#pragma unroll 4
    for (int r = 0; r < 256; r++) {
        float v = yp[(size_t)r * EE];
        s += v;
        q += v * v;
    }
    g_psum[blk * EE + e] = s;
    g_psq[blk * EE + e] = q;
}

__global__ void stats2_k(int nrows) {
    int e = threadIdx.x;
    float s = 0.f, q = 0.f;
#pragma unroll 4
    for (int blk = 0; blk < nrows; blk++) {
        s += g_psum[blk * EE + e];
        q += g_psq[blk * EE + e];
    }
    g_sum[e] = s;
    g_sq[e] = q;
}

// ---------------- BN apply + LIF (prefetch depth 8) ----------------------------
__global__ void lif_k(const float* __restrict__ gamma, const float* __restrict__ beta,
                      int write_rate) {
    int b = blockIdx.x >> 2;
    int e = ((blockIdx.x & 3) << 6) + threadIdx.x;   // blockDim = 64
    float mu = g_sum[e] * (1.f / NROW);
    float var = g_sq[e] * (1.f / NROW) - mu * mu;
    float sc = gamma[e] / sqrtf(var + 1e-5f);
    float sh = fmaf(-mu, sc, beta[e]);

    const float* yp = g_y + b * 256 + e;
    __half* sp = g_spad + ROWSTRIDE + b * 256 + e;

    float buf[8];
#pragma unroll
    for (int i = 0; i < 8; i++) buf[i] = yp[(size_t)i * ROWSTRIDE];
    float v = 0.f, cnt = 0.f;
#pragma unroll 8
    for (int t = 0; t < TT; t++) {
        float xv = buf[t & 7];
        if (t + 8 < TT) buf[t & 7] = yp[(size_t)(t + 8) * ROWSTRIDE];
        float yn = fmaf(xv, sc, sh);
        v = 0.5f * (v + yn);
        float s = (v >= 1.f) ? 1.f : 0.f;
        sp[(size_t)t * ROWSTRIDE] = __float2half(s);
        cnt += s;
        v = (v >= 1.f) ? 0.f : v;
    }
    if (write_rate) g_rate[b * 256 + e] = cnt * (1.f / TT);
}

// ---------------- head ----------------------------------------------------------
__global__ void head_k(const float* __restrict__ hw, const float* __restrict__ hb,
                       float* __restrict__ out) {
    __shared__ float rs[EE];
    int b = blockIdx.x, tid = threadIdx.x;   // 64 threads
    for (int j = tid; j < EE; j += 64) rs[j] = g_rate[b * EE + j];
    __syncthreads();
    if (tid < OUTD) {
        float acc = hb[tid];
#pragma unroll 8
        for (int e2 = 0; e2 < EE; e2++) acc += rs[e2] * hw[tid * EE + e2];
        out[b * OUTD + tid] = acc;
    }
}

// ---------------- launch ---------------------------------------------------------
extern "C" void kernel_launch(void* const* d_in, const int* in_sizes, int n_in,
                              void* d_out, int out_size) {
    const float *x = 0, *conv0_w = 0, *conv0_b = 0, *convs_w = 0, *convs_b = 0;
    const float *gamma = 0, *beta = 0, *head_w = 0, *head_b = 0;
    int n1024_seen = 0;
    int alphabetical = (n_in > 0 && in_sizes[0] == 1024);
    for (int i = 0; i < n_in; i++) {
        const float* p = (const float*)d_in[i];
        switch (in_sizes[i]) {
            case 524288: x = p; break;
            case 6144:   conv0_w = p; break;
            case 256:    conv0_b = p; break;
            case 589824: convs_w = p; break;
            case 768:    convs_b = p; break;
            case 16128:  head_w = p; break;
            case 63:     head_b = p; break;
            case 1024:
                if (n1024_seen == 0) { if (alphabetical) beta = p; else gamma = p; }
                else                 { if (alphabetical) gamma = p; else beta = p; }
                n1024_seen++;
                break;
            default: break;
        }
    }
    float* out = (float*)d_out;

    cudaFuncSetAttribute(conv_mma_k, cudaFuncAttributeMaxDynamicSharedMemorySize, SMEM_BYTES);

    repack_wh_k<<<(3 * 768 * 256 + 255) / 256, 256>>>(convs_w);
    repack_w0_k<<<(3 * CIN * 256 + 255) / 256, 256>>>(conv0_w);
    zero_pads_k<<<(2 * ROWSTRIDE + 255) / 256, 256>>>();

    // block 0
    conv0_k<<<TT * 4, 256>>>(x, conv0_b);
    stats1_k<<<256, 256>>>();
    stats2_k<<<1, 256>>>(256);
    lif_k<<<BB * 4, 64>>>(gamma + 0 * EE, beta + 0 * EE, 0);

    // blocks 1..3 (fp16 scaled-2-split tensor-core GEMM, stats fused in epilogue)
    for (int i = 0; i < 3; i++) {
        conv_mma_k<<<dim3(2, 512), 256, SMEM_BYTES>>>(i, convs_b + i * EE);
        stats2_k<<<1, 256>>>(512);
        lif_k<<<BB * 4, 64>>>(gamma + (i + 1) * EE, beta + (i + 1) * EE, (i == 2) ? 1 : 0);
    }

    head_k<<<BB, 64>>>(head_w, head_b, out);
}

// round 8
// speedup vs baseline: 3.6650x; 1.0228x over previous
#include <cuda_runtime.h>
#include <cuda_fp16.h>
#include <cstdint>

#define BB 64
#define TT 1024
#define EE 256
#define CIN 8
#define OUTD 63
#define NROW (BB*TT)          // 65536
#define ROWSTRIDE (BB*EE)     // 16384

#define LO_SCALE 4096.f
#define LO_INV   (1.f/4096.f)

// ---------------- scratch ----------------------------------------------------
__device__ float g_y[NROW * EE];                                // conv out [(t*B+b)][e]
__device__ __align__(16) __half g_spad[(TT + 2) * ROWSTRIDE];   // fp16 spikes, t-padded
__device__ __align__(16) __half g_wh[3 * 2 * 768 * 256];        // fp16 weights [layer][split][k][n]
__device__ float g_w0[3 * CIN * EE];
__device__ float g_psum[512 * EE];
__device__ float g_psq[512 * EE];
__device__ float g_sum[EE];
__device__ float g_sq[EE];
__device__ float g_rate[BB * EE];

// ---------------- ptx helpers ------------------------------------------------
__device__ __forceinline__ uint32_t smem_u32(const void* p) {
    uint32_t a;
    asm("{ .reg .u64 t; cvta.to.shared.u64 t, %1; cvt.u32.u64 %0, t; }" : "=r"(a) : "l"(p));
    return a;
}
__device__ __forceinline__ void ldm4(uint32_t* r, uint32_t a) {
    asm volatile("ldmatrix.sync.aligned.m8n8.x4.shared.b16 {%0,%1,%2,%3}, [%4];"
                 : "=r"(r[0]), "=r"(r[1]), "=r"(r[2]), "=r"(r[3]) : "r"(a));
}
__device__ __forceinline__ void ldm4t(uint32_t* r, uint32_t a) {
    asm volatile("ldmatrix.sync.aligned.m8n8.x4.trans.shared.b16 {%0,%1,%2,%3}, [%4];"
                 : "=r"(r[0]), "=r"(r[1]), "=r"(r[2]), "=r"(r[3]) : "r"(a));
}
__device__ __forceinline__ void mma_h(float* d, const uint32_t* a, const uint32_t* b) {
    asm volatile("mma.sync.aligned.m16n8k16.row.col.f32.f16.f16.f32 "
                 "{%0,%1,%2,%3}, {%4,%5,%6,%7}, {%8,%9}, {%0,%1,%2,%3};"
                 : "+f"(d[0]), "+f"(d[1]), "+f"(d[2]), "+f"(d[3])
                 : "r"(a[0]), "r"(a[1]), "r"(a[2]), "r"(a[3]), "r"(b[0]), "r"(b[1]));
}
__device__ __forceinline__ void cpa16(uint32_t dst, const void* src) {
    asm volatile("cp.async.cg.shared.global [%0], [%1], 16;" :: "r"(dst), "l"(src));
}
#define CPA_COMMIT() asm volatile("cp.async.commit_group;" ::: "memory")
#define CPA_WAIT2()  asm volatile("cp.async.wait_group 2;" ::: "memory")

// ---------------- prep kernels -----------------------------------------------
__global__ void repack_wh_k(const float* __restrict__ w) {
    int idx = blockIdx.x * blockDim.x + threadIdx.x;     // 3*768*256
    if (idx >= 3 * 768 * 256) return;
    int n = idx & 255;
    int k = (idx >> 8) % 768;          // k = kpos*256 + c
    int i = idx / (768 * 256);
    int kpos = k >> 8;
    int c = k & 255;
    float wf = w[((i * 256 + n) * 256 + c) * 3 + kpos];
    __half h0 = __float2half_rn(wf);
    float lo = (wf - __half2float(h0)) * LO_SCALE;       // residual lifted to normal range
    __half h1 = __float2half_rn(lo);
    g_wh[((size_t)(i * 2 + 0) * 768 + k) * 256 + n] = h0;
    g_wh[((size_t)(i * 2 + 1) * 768 + k) * 256 + n] = h1;
}

__global__ void repack_w0_k(const float* __restrict__ w0) {
    int idx = blockIdx.x * blockDim.x + threadIdx.x;
    if (idx >= 3 * CIN * 256) return;
    int o = idx & 255;
    int c = (idx >> 8) & 7;
    int k = idx >> 11;
    g_w0[idx] = w0[(o * CIN + c) * 3 + k];
}

__global__ void zero_pads_k() {
    int idx = blockIdx.x * blockDim.x + threadIdx.x;
    if (idx < ROWSTRIDE) g_spad[idx] = __float2half(0.f);
    else if (idx < 2 * ROWSTRIDE) g_spad[(TT + 1) * ROWSTRIDE + (idx - ROWSTRIDE)] = __float2half(0.f);
}

// ---------------- conv0 (fp32, small K) ---------------------------------------
__global__ void conv0_k(const float* __restrict__ x, const float* __restrict__ bias) {
    __shared__ float ws[24 * 256];
    __shared__ float xs[16][24];
    int t = blockIdx.x >> 2;
    int b0 = (blockIdx.x & 3) * 16;
    int tid = threadIdx.x;
#pragma unroll
    for (int j = 0; j < 24; j++) ws[j * 256 + tid] = g_w0[j * 256 + tid];
    for (int q = tid; q < 384; q += 256) {
        int bl = q / 24, rem = q % 24;
        int k = rem >> 3, c = rem & 7;
        int ttm = t - 1 + k;
        float v = 0.f;
        if (ttm >= 0 && ttm < TT) v = x[((b0 + bl) * TT + ttm) * CIN + c];
        xs[bl][rem] = v;
    }
    __syncthreads();
    int o = tid;
    float bo = bias[o];
    for (int r = 0; r < 16; r++) {
        float acc = bo;
#pragma unroll
        for (int j = 0; j < 24; j++) acc += ws[j * 256 + o] * xs[r][j];
        g_y[(size_t)(t * BB + b0 + r) * EE + o] = acc;
    }
}

// ---------------- fp16 scaled-2-split MMA conv GEMM (512 thr, cp.async x4) ------
// CTA tile 128m x 128n; 16 warps, each 32x32. K = 768 x 2 splits, chunks of 32.
#define APITCH 40
#define BPITCH 136
#define A_H 5120                        // halves: A tile per stage (128*40)
#define B_SP 4352                       // halves: one split B tile (32*136)
#define ST_H (A_H + 2 * B_SP)           // 13824 halves per stage
#define NSTAGE 4
#define SMEM_HALVES (NSTAGE * ST_H)     // 55296
#define SMEM_BYTES (SMEM_HALVES * 2)    // 110592

__global__ void __launch_bounds__(512, 1) conv_mma_k(int layer, const float* __restrict__ bias) {
    extern __shared__ __half sm[];
    const int tid = threadIdx.x;
    const int lane = tid & 31;
    const int wid = tid >> 5;
    const int wm = wid & 3;          // warp M group (32 rows)
    const int wn = wid >> 2;         // warp N group (32 cols)
    const int mt = blockIdx.y;       // 512 M tiles
    const int nb = blockIdx.x;       // 2 N tiles

    const uint4* __restrict__ wsrc = (const uint4*)(g_wh + (size_t)layer * 2 * 768 * 256);

    float acch[2][4][4], accl[2][4][4];
#pragma unroll
    for (int mi = 0; mi < 2; mi++)
#pragma unroll
        for (int u = 0; u < 4; u++)
#pragma unroll
            for (int q = 0; q < 4; q++) { acch[mi][u][q] = 0.f; accl[mi][u][q] = 0.f; }

    // per-thread cp.async coords
    const int arow = tid >> 2;        // 0..127
    const int aq = tid & 3;           // 16B quarter of 64B A row
    const uint32_t smb = smem_u32(sm);

    // issue one K-chunk of loads into a stage
    auto issue = [&](int ck, int st) {
        int kpos = ck >> 3, c0 = (ck & 7) << 5;
        uint32_t base = smb + (uint32_t)(st * ST_H) * 2;
        // A: 512 x 16B
        cpa16(base + (arow * APITCH + aq * 8) * 2,
              g_spad + (size_t)(2 * mt + (arow >> 6) + kpos) * ROWSTRIDE + (arow & 63) * 256 + c0 + aq * 8);
        // B: 1024 x 16B (2 per thread)
#pragma unroll
        for (int it = 0; it < 2; it++) {
            int u = tid + it * 512;
            int s = u >> 9, rest = u & 511;
            int kk = rest >> 4, g = rest & 15;
            cpa16(base + (A_H + s * B_SP + kk * BPITCH + g * 8) * 2,
                  wsrc + (size_t)(s * 768 + kpos * 256 + c0 + kk) * 32 + nb * 16 + g);
        }
    };

    // prologue: stages 0..2
#pragma unroll
    for (int p = 0; p < 3; p++) { issue(p, p); CPA_COMMIT(); }

    for (int ck = 0; ck < 24; ck++) {
        CPA_WAIT2();
        __syncthreads();
        if (ck + 3 < 24) issue(ck + 3, (ck + 3) & 3);
        CPA_COMMIT();

        const __half* Asm = sm + (ck & 3) * ST_H;
        const __half* Bsm = Asm + A_H;
#pragma unroll
        for (int kh = 0; kh < 2; kh++) {
            uint32_t afr[2][4];
#pragma unroll
            for (int mi = 0; mi < 2; mi++) {
                uint32_t ad = smem_u32(Asm + (wm * 32 + mi * 16 + (lane & 15)) * APITCH
                                       + kh * 16 + (lane >> 4) * 8);
                ldm4(afr[mi], ad);
            }
#pragma unroll
            for (int s = 0; s < 2; s++) {
                uint32_t bfr[2][4];
#pragma unroll
                for (int q = 0; q < 2; q++) {
                    uint32_t bd = smem_u32(Bsm + s * B_SP + (kh * 16 + (lane & 15)) * BPITCH
                                           + wn * 32 + q * 16 + (lane >> 4) * 8);
                    ldm4t(bfr[q], bd);
                }
                if (s == 0) {
#pragma unroll
                    for (int mi = 0; mi < 2; mi++)
#pragma unroll
                        for (int q = 0; q < 2; q++)
#pragma unroll
                            for (int h = 0; h < 2; h++)
                                mma_h(acch[mi][q * 2 + h], afr[mi], &bfr[q][h * 2]);
                } else {
#pragma unroll
                    for (int mi = 0; mi < 2; mi++)
#pragma unroll
                        for (int q = 0; q < 2; q++)
#pragma unroll
                            for (int h = 0; h < 2; h++)
                                mma_h(accl[mi][q * 2 + h], afr[mi], &bfr[q][h * 2]);
                }
            }
        }
    }

    // ---------------- epilogue: combine splits, write y, fused column stats ------
    __syncthreads();                        // smem free for reuse
    float* red = (float*)sm;                // [wm][128] sums, then [512..1024) sq

    const int m0 = mt * 128 + wm * 32 + (lane >> 2);
    float csum[8], csq[8];
#pragma unroll
    for (int j = 0; j < 8; j++) { csum[j] = 0.f; csq[j] = 0.f; }

#pragma unroll
    for (int u = 0; u < 4; u++) {
        int n = nb * 128 + wn * 32 + (u >> 1) * 16 + (u & 1) * 8 + (lane & 3) * 2;
        float2 bv = *(const float2*)(bias + n);
#pragma unroll
        for (int mi = 0; mi < 2; mi++) {
            int r0 = m0 + mi * 16;
            float v00 = fmaf(accl[mi][u][0], LO_INV, acch[mi][u][0]) + bv.x;
            float v01 = fmaf(accl[mi][u][1], LO_INV, acch[mi][u][1]) + bv.y;
            float v10 = fmaf(accl[mi][u][2], LO_INV, acch[mi][u][2]) + bv.x;
            float v11 = fmaf(accl[mi][u][3], LO_INV, acch[mi][u][3]) + bv.y;
            float2 w0, w1;
            w0.x = v00; w0.y = v01;
            w1.x = v10; w1.y = v11;
            *(float2*)(g_y + (size_t)r0 * 256 + n) = w0;
            *(float2*)(g_y + (size_t)(r0 + 8) * 256 + n) = w1;
            csum[u * 2 + 0] += v00 + v10;
            csum[u * 2 + 1] += v01 + v11;
            csq[u * 2 + 0] += v00 * v00 + v10 * v10;
            csq[u * 2 + 1] += v01 * v01 + v11 * v11;
        }
    }
    // reduce over the 8 row-lanes (bits 2..4 of lane)
#pragma unroll
    for (int off = 4; off < 32; off <<= 1)
#pragma unroll
        for (int j = 0; j < 8; j++) {
            csum[j] += __shfl_xor_sync(0xffffffffu, csum[j], off);
            csq[j]  += __shfl_xor_sync(0xffffffffu, csq[j],  off);
        }
    if (lane < 4) {
#pragma unroll
        for (int j = 0; j < 8; j++) {
            int u = j >> 1;
            int cl = wn * 32 + (u >> 1) * 16 + (u & 1) * 8 + lane * 2 + (j & 1);  // 0..127
            red[wm * 128 + cl] = csum[j];
            red[512 + wm * 128 + cl] = csq[j];
        }
    }
    __syncthreads();
    if (tid < 128) {
        float s = red[tid] + red[128 + tid] + red[256 + tid] + red[384 + tid];
        float q = red[512 + tid] + red[640 + tid] + red[768 + tid] + red[896 + tid];
        g_psum[mt * 256 + nb * 128 + tid] = s;
        g_psq[mt * 256 + nb * 128 + tid] = q;
    }
}

// ---------------- BN stats (layer 0 path + shared finalize) --------------------
__global__ void stats1_k() {
    int e = threadIdx.x;
    int blk = blockIdx.x;
    const float* yp = g_y + (size_t)(blk * 256) * EE + e;
    float s = 0.f, q = 0.f;
#pragma unroll 4
    for (int r = 0; r < 256; r++) {
        float v = yp[(size_t)r * EE];
        s += v;
        q += v * v;
    }
    g_psum[blk * EE + e] = s;
    g_psq[blk * EE + e] = q;
}

__global__ void stats2_k(int nrows) {
    int e = threadIdx.x;
    float s = 0.f, q = 0.f;
#pragma unroll 4
    for (int blk = 0; blk < nrows; blk++) {
        s += g_psum[blk * EE + e];
        q += g_psq[blk * EE + e];
    }
    g_sum[e] = s;
    g_sq[e] = q;
}

// ---------------- BN apply + LIF (prefetch depth 8) ----------------------------
__global__ void lif_k(const float* __restrict__ gamma, const float* __restrict__ beta,
                      int write_rate) {
    int b = blockIdx.x >> 2;
    int e = ((blockIdx.x & 3) << 6) + threadIdx.x;   // blockDim = 64
    float mu = g_sum[e] * (1.f / NROW);
    float var = g_sq[e] * (1.f / NROW) - mu * mu;
    float sc = gamma[e] / sqrtf(var + 1e-5f);
    float sh = fmaf(-mu, sc, beta[e]);

    const float* yp = g_y + b * 256 + e;
    __half* sp = g_spad + ROWSTRIDE + b * 256 + e;

    float buf[8];
#pragma unroll
    for (int i = 0; i < 8; i++) buf[i] = yp[(size_t)i * ROWSTRIDE];
    float v = 0.f, cnt = 0.f;
#pragma unroll 8
    for (int t = 0; t < TT; t++) {
        float xv = buf[t & 7];
        if (t + 8 < TT) buf[t & 7] = yp[(size_t)(t + 8) * ROWSTRIDE];
        float yn = fmaf(xv, sc, sh);
        v = 0.5f * (v + yn);
        float s = (v >= 1.f) ? 1.f : 0.f;
        sp[(size_t)t * ROWSTRIDE] = __float2half(s);
        cnt += s;
        v = (v >= 1.f) ? 0.f : v;
    }
    if (write_rate) g_rate[b * 256 + e] = cnt * (1.f / TT);
}

// ---------------- head ----------------------------------------------------------
__global__ void head_k(const float* __restrict__ hw, const float* __restrict__ hb,
                       float* __restrict__ out) {
    __shared__ float rs[EE];
    int b = blockIdx.x, tid = threadIdx.x;   // 64 threads
    for (int j = tid; j < EE; j += 64) rs[j] = g_rate[b * EE + j];
    __syncthreads();
    if (tid < OUTD) {
        float acc = hb[tid];
#pragma unroll 8
        for (int e2 = 0; e2 < EE; e2++) acc += rs[e2] * hw[tid * EE + e2];
        out[b * OUTD + tid] = acc;
    }
}

// ---------------- launch ---------------------------------------------------------
extern "C" void kernel_launch(void* const* d_in, const int* in_sizes, int n_in,
                              void* d_out, int out_size) {
    const float *x = 0, *conv0_w = 0, *conv0_b = 0, *convs_w = 0, *convs_b = 0;
    const float *gamma = 0, *beta = 0, *head_w = 0, *head_b = 0;
    int n1024_seen = 0;
    int alphabetical = (n_in > 0 && in_sizes[0] == 1024);
    for (int i = 0; i < n_in; i++) {
        const float* p = (const float*)d_in[i];
        switch (in_sizes[i]) {
            case 524288: x = p; break;
            case 6144:   conv0_w = p; break;
            case 256:    conv0_b = p; break;
            case 589824: convs_w = p; break;
            case 768:    convs_b = p; break;
            case 16128:  head_w = p; break;
            case 63:     head_b = p; break;
            case 1024:
                if (n1024_seen == 0) { if (alphabetical) beta = p; else gamma = p; }
                else                 { if (alphabetical) gamma = p; else beta = p; }
                n1024_seen++;
                break;
            default: break;
        }
    }
    float* out = (float*)d_out;

    cudaFuncSetAttribute(conv_mma_k, cudaFuncAttributeMaxDynamicSharedMemorySize, SMEM_BYTES);

    repack_wh_k<<<(3 * 768 * 256 + 255) / 256, 256>>>(convs_w);
    repack_w0_k<<<(3 * CIN * 256 + 255) / 256, 256>>>(conv0_w);
    zero_pads_k<<<(2 * ROWSTRIDE + 255) / 256, 256>>>();

    // block 0
    conv0_k<<<TT * 4, 256>>>(x, conv0_b);
    stats1_k<<<256, 256>>>();
    stats2_k<<<1, 256>>>(256);
    lif_k<<<BB * 4, 64>>>(gamma + 0 * EE, beta + 0 * EE, 0);

    // blocks 1..3 (fp16 scaled-2-split GEMM, 512 thr, cp.async 4-stage, fused stats)
    for (int i = 0; i < 3; i++) {
        conv_mma_k<<<dim3(2, 512), 512, SMEM_BYTES>>>(i, convs_b + i * EE);
        stats2_k<<<1, 256>>>(512);
        lif_k<<<BB * 4, 64>>>(gamma + (i + 1) * EE, beta + (i + 1) * EE, (i == 2) ? 1 : 0);
    }

    head_k<<<BB, 64>>>(head_w, head_b, out);
}

// round 9
// speedup vs baseline: 4.2182x; 1.1510x over previous
#include <cuda_runtime.h>
#include <cuda_fp16.h>
#include <cstdint>

#define BB 64
#define TT 1024
#define EE 256
#define CIN 8
#define OUTD 63
#define NROW (BB*TT)          // 65536
#define ROWSTRIDE (BB*EE)     // 16384

#define LO_SCALE 4096.f
#define LO_INV   (1.f/4096.f)

// ---------------- scratch ----------------------------------------------------
__device__ float g_y[NROW * EE];                                // conv out [(t*B+b)][e]
__device__ __align__(16) __half g_spad[(TT + 2) * ROWSTRIDE];   // fp16 spikes, t-padded
__device__ __align__(16) __half g_wh[3 * 2 * 768 * 256];        // fp16 weights [layer][split][k][n]
__device__ float g_w0[3 * CIN * EE];
__device__ float g_psum[EE * 512];                              // TRANSPOSED: [e][row]
__device__ float g_psq[EE * 512];
__device__ float g_sum[EE];
__device__ float g_sq[EE];
__device__ float g_rate[BB * EE];

// ---------------- ptx helpers ------------------------------------------------
__device__ __forceinline__ uint32_t smem_u32(const void* p) {
    uint32_t a;
    asm("{ .reg .u64 t; cvta.to.shared.u64 t, %1; cvt.u32.u64 %0, t; }" : "=r"(a) : "l"(p));
    return a;
}
__device__ __forceinline__ void ldm4(uint32_t* r, uint32_t a) {
    asm volatile("ldmatrix.sync.aligned.m8n8.x4.shared.b16 {%0,%1,%2,%3}, [%4];"
                 : "=r"(r[0]), "=r"(r[1]), "=r"(r[2]), "=r"(r[3]) : "r"(a));
}
__device__ __forceinline__ void ldm4t(uint32_t* r, uint32_t a) {
    asm volatile("ldmatrix.sync.aligned.m8n8.x4.trans.shared.b16 {%0,%1,%2,%3}, [%4];"
                 : "=r"(r[0]), "=r"(r[1]), "=r"(r[2]), "=r"(r[3]) : "r"(a));
}
__device__ __forceinline__ void mma_h(float* d, const uint32_t* a, const uint32_t* b) {
    asm volatile("mma.sync.aligned.m16n8k16.row.col.f32.f16.f16.f32 "
                 "{%0,%1,%2,%3}, {%4,%5,%6,%7}, {%8,%9}, {%0,%1,%2,%3};"
                 : "+f"(d[0]), "+f"(d[1]), "+f"(d[2]), "+f"(d[3])
                 : "r"(a[0]), "r"(a[1]), "r"(a[2]), "r"(a[3]), "r"(b[0]), "r"(b[1]));
}
__device__ __forceinline__ void cpa16(uint32_t dst, const void* src) {
    asm volatile("cp.async.cg.shared.global [%0], [%1], 16;" :: "r"(dst), "l"(src));
}
#define CPA_COMMIT() asm volatile("cp.async.commit_group;" ::: "memory")
#define CPA_WAIT2()  asm volatile("cp.async.wait_group 2;" ::: "memory")

// ---------------- prep kernels -----------------------------------------------
__global__ void repack_wh_k(const float* __restrict__ w) {
    int idx = blockIdx.x * blockDim.x + threadIdx.x;     // 3*768*256
    if (idx >= 3 * 768 * 256) return;
    int n = idx & 255;
    int k = (idx >> 8) % 768;          // k = kpos*256 + c
    int i = idx / (768 * 256);
    int kpos = k >> 8;
    int c = k & 255;
    float wf = w[((i * 256 + n) * 256 + c) * 3 + kpos];
    __half h0 = __float2half_rn(wf);
    float lo = (wf - __half2float(h0)) * LO_SCALE;       // residual lifted to normal range
    __half h1 = __float2half_rn(lo);
    g_wh[((size_t)(i * 2 + 0) * 768 + k) * 256 + n] = h0;
    g_wh[((size_t)(i * 2 + 1) * 768 + k) * 256 + n] = h1;
}

// merged: conv0 weight repack + spad time-pad zeroing
__global__ void prep_k(const float* __restrict__ w0) {
    int idx = blockIdx.x * blockDim.x + threadIdx.x;     // grid covers 2*ROWSTRIDE
    if (idx < ROWSTRIDE) g_spad[idx] = __float2half(0.f);
    else if (idx < 2 * ROWSTRIDE) g_spad[(TT + 1) * ROWSTRIDE + (idx - ROWSTRIDE)] = __float2half(0.f);
    if (idx < 3 * CIN * 256) {
        int o = idx & 255;
        int c = (idx >> 8) & 7;
        int k = idx >> 11;
        g_w0[idx] = w0[(o * CIN + c) * 3 + k];
    }
}

// ---------------- conv0: one CTA per t, weights in registers -------------------
__global__ void __launch_bounds__(256) conv0_k(const float* __restrict__ x,
                                               const float* __restrict__ bias) {
    __shared__ float xs[64][24];
    int t = blockIdx.x;
    int tid = threadIdx.x;
    // weights for output channel o=tid: 24 registers
    float wr[24];
#pragma unroll
    for (int j = 0; j < 24; j++) wr[j] = g_w0[j * 256 + tid];
    // inputs: 64 b x (3 k x 8 c)
    for (int q = tid; q < 64 * 24; q += 256) {
        int bl = q / 24, rem = q % 24;
        int k = rem >> 3, c = rem & 7;
        int ttm = t - 1 + k;
        float v = 0.f;
        if (ttm >= 0 && ttm < TT) v = x[((bl) * TT + ttm) * CIN + c];
        xs[bl][rem] = v;
    }
    __syncthreads();
    float bo = bias[tid];
#pragma unroll 2
    for (int r = 0; r < 64; r++) {
        float acc = bo;
#pragma unroll
        for (int j = 0; j < 24; j++) acc += wr[j] * xs[r][j];
        g_y[(size_t)(t * BB + r) * EE + tid] = acc;
    }
}

// ---------------- fp16 scaled-2-split MMA conv GEMM (512 thr, cp.async x4) ------
// CTA tile 128m x 128n; 16 warps, each 32x32. K = 768 x 2 splits, chunks of 32.
#define APITCH 40
#define BPITCH 136
#define A_H 5120                        // halves: A tile per stage (128*40)
#define B_SP 4352                       // halves: one split B tile (32*136)
#define ST_H (A_H + 2 * B_SP)           // 13824 halves per stage
#define NSTAGE 4
#define SMEM_HALVES (NSTAGE * ST_H)     // 55296
#define SMEM_BYTES (SMEM_HALVES * 2)    // 110592

__global__ void __launch_bounds__(512, 1) conv_mma_k(int layer, const float* __restrict__ bias) {
    extern __shared__ __half sm[];
    const int tid = threadIdx.x;
    const int lane = tid & 31;
    const int wid = tid >> 5;
    const int wm = wid & 3;          // warp M group (32 rows)
    const int wn = wid >> 2;         // warp N group (32 cols)
    const int mt = blockIdx.y;       // 512 M tiles
    const int nb = blockIdx.x;       // 2 N tiles

    const uint4* __restrict__ wsrc = (const uint4*)(g_wh + (size_t)layer * 2 * 768 * 256);

    float acch[2][4][4], accl[2][4][4];
#pragma unroll
    for (int mi = 0; mi < 2; mi++)
#pragma unroll
        for (int u = 0; u < 4; u++)
#pragma unroll
            for (int q = 0; q < 4; q++) { acch[mi][u][q] = 0.f; accl[mi][u][q] = 0.f; }

    const int arow = tid >> 2;        // 0..127
    const int aq = tid & 3;           // 16B quarter of 64B A row
    const uint32_t smb = smem_u32(sm);

    auto issue = [&](int ck, int st) {
        int kpos = ck >> 3, c0 = (ck & 7) << 5;
        uint32_t base = smb + (uint32_t)(st * ST_H) * 2;
        cpa16(base + (arow * APITCH + aq * 8) * 2,
              g_spad + (size_t)(2 * mt + (arow >> 6) + kpos) * ROWSTRIDE + (arow & 63) * 256 + c0 + aq * 8);
#pragma unroll
        for (int it = 0; it < 2; it++) {
            int u = tid + it * 512;
            int s = u >> 9, rest = u & 511;
            int kk = rest >> 4, g = rest & 15;
            cpa16(base + (A_H + s * B_SP + kk * BPITCH + g * 8) * 2,
                  wsrc + (size_t)(s * 768 + kpos * 256 + c0 + kk) * 32 + nb * 16 + g);
        }
    };

#pragma unroll
    for (int p = 0; p < 3; p++) { issue(p, p); CPA_COMMIT(); }

    for (int ck = 0; ck < 24; ck++) {
        CPA_WAIT2();
        __syncthreads();
        if (ck + 3 < 24) issue(ck + 3, (ck + 3) & 3);
        CPA_COMMIT();

        const __half* Asm = sm + (ck & 3) * ST_H;
        const __half* Bsm = Asm + A_H;
#pragma unroll
        for (int kh = 0; kh < 2; kh++) {
            uint32_t afr[2][4];
#pragma unroll
            for (int mi = 0; mi < 2; mi++) {
                uint32_t ad = smem_u32(Asm + (wm * 32 + mi * 16 + (lane & 15)) * APITCH
                                       + kh * 16 + (lane >> 4) * 8);
                ldm4(afr[mi], ad);
            }
#pragma unroll
            for (int s = 0; s < 2; s++) {
                uint32_t bfr[2][4];
#pragma unroll
                for (int q = 0; q < 2; q++) {
                    uint32_t bd = smem_u32(Bsm + s * B_SP + (kh * 16 + (lane & 15)) * BPITCH
                                           + wn * 32 + q * 16 + (lane >> 4) * 8);
                    ldm4t(bfr[q], bd);
                }
                if (s == 0) {
#pragma unroll
                    for (int mi = 0; mi < 2; mi++)
#pragma unroll
                        for (int q = 0; q < 2; q++)
#pragma unroll
                            for (int h = 0; h < 2; h++)
                                mma_h(acch[mi][q * 2 + h], afr[mi], &bfr[q][h * 2]);
                } else {
#pragma unroll
                    for (int mi = 0; mi < 2; mi++)
#pragma unroll
                        for (int q = 0; q < 2; q++)
#pragma unroll
                            for (int h = 0; h < 2; h++)
                                mma_h(accl[mi][q * 2 + h], afr[mi], &bfr[q][h * 2]);
                }
            }
        }
    }

    // ---------------- epilogue: combine splits, write y, fused column stats ------
    __syncthreads();
    float* red = (float*)sm;

    const int m0 = mt * 128 + wm * 32 + (lane >> 2);
    float csum[8], csq[8];
#pragma unroll
    for (int j = 0; j < 8; j++) { csum[j] = 0.f; csq[j] = 0.f; }

#pragma unroll
    for (int u = 0; u < 4; u++) {
        int n = nb * 128 + wn * 32 + (u >> 1) * 16 + (u & 1) * 8 + (lane & 3) * 2;
        float2 bv = *(const float2*)(bias + n);
#pragma unroll
        for (int mi = 0; mi < 2; mi++) {
            int r0 = m0 + mi * 16;
            float v00 = fmaf(accl[mi][u][0], LO_INV, acch[mi][u][0]) + bv.x;
            float v01 = fmaf(accl[mi][u][1], LO_INV, acch[mi][u][1]) + bv.y;
            float v10 = fmaf(accl[mi][u][2], LO_INV, acch[mi][u][2]) + bv.x;
            float v11 = fmaf(accl[mi][u][3], LO_INV, acch[mi][u][3]) + bv.y;
            float2 w0, w1;
            w0.x = v00; w0.y = v01;
            w1.x = v10; w1.y = v11;
            *(float2*)(g_y + (size_t)r0 * 256 + n) = w0;
            *(float2*)(g_y + (size_t)(r0 + 8) * 256 + n) = w1;
            csum[u * 2 + 0] += v00 + v10;
            csum[u * 2 + 1] += v01 + v11;
            csq[u * 2 + 0] += v00 * v00 + v10 * v10;
            csq[u * 2 + 1] += v01 * v01 + v11 * v11;
        }
    }
#pragma unroll
    for (int off = 4; off < 32; off <<= 1)
#pragma unroll
        for (int j = 0; j < 8; j++) {
            csum[j] += __shfl_xor_sync(0xffffffffu, csum[j], off);
            csq[j]  += __shfl_xor_sync(0xffffffffu, csq[j],  off);
        }
    if (lane < 4) {
#pragma unroll
        for (int j = 0; j < 8; j++) {
            int u = j >> 1;
            int cl = wn * 32 + (u >> 1) * 16 + (u & 1) * 8 + lane * 2 + (j & 1);  // 0..127
            red[wm * 128 + cl] = csum[j];
            red[512 + wm * 128 + cl] = csq[j];
        }
    }
    __syncthreads();
    if (tid < 128) {
        float s = red[tid] + red[128 + tid] + red[256 + tid] + red[384 + tid];
        float q = red[512 + tid] + red[640 + tid] + red[768 + tid] + red[896 + tid];
        // TRANSPOSED partials: [e][row]
        g_psum[(size_t)(nb * 128 + tid) * 512 + mt] = s;
        g_psq[(size_t)(nb * 128 + tid) * 512 + mt] = q;
    }
}

// ---------------- BN stats -----------------------------------------------------
// layer-0 partials (transposed write)
__global__ void stats1_k() {
    int e = threadIdx.x;
    int blk = blockIdx.x;                     // 256 blocks x 256 rows
    const float* yp = g_y + (size_t)(blk * 256) * EE + e;
    float s = 0.f, q = 0.f;
#pragma unroll 4
    for (int r = 0; r < 256; r++) {
        float v = yp[(size_t)r * EE];
        s += v;
        q += v * v;
    }
    g_psum[(size_t)e * 512 + blk] = s;
    g_psq[(size_t)e * 512 + blk] = q;
}

// parallel deterministic finalize: 1 block per channel
__global__ void __launch_bounds__(128) stats2_k(int nrows) {
    __shared__ float ss[128], qq[128];
    int e = blockIdx.x;
    int t = threadIdx.x;
    const float* ps = g_psum + (size_t)e * 512;
    const float* pq = g_psq + (size_t)e * 512;
    float s = 0.f, q = 0.f;
    for (int r = t; r < nrows; r += 128) { s += ps[r]; q += pq[r]; }
    ss[t] = s; qq[t] = q;
    __syncthreads();
#pragma unroll
    for (int off = 64; off > 0; off >>= 1) {
        if (t < off) { ss[t] += ss[t + off]; qq[t] += qq[t + off]; }
        __syncthreads();
    }
    if (t == 0) { g_sum[e] = ss[0]; g_sq[e] = qq[0]; }
}

// ---------------- BN apply + LIF (prefetch depth 8) ----------------------------
__global__ void lif_k(const float* __restrict__ gamma, const float* __restrict__ beta,
                      int write_rate) {
    int b = blockIdx.x >> 2;
    int e = ((blockIdx.x & 3) << 6) + threadIdx.x;   // blockDim = 64
    float mu = g_sum[e] * (1.f / NROW);
    float var = g_sq[e] * (1.f / NROW) - mu * mu;
    float sc = gamma[e] / sqrtf(var + 1e-5f);
    float sh = fmaf(-mu, sc, beta[e]);

    const float* yp = g_y + b * 256 + e;
    __half* sp = g_spad + ROWSTRIDE + b * 256 + e;

    float buf[8];
#pragma unroll
    for (int i = 0; i < 8; i++) buf[i] = yp[(size_t)i * ROWSTRIDE];
    float v = 0.f, cnt = 0.f;
#pragma unroll 8
    for (int t = 0; t < TT; t++) {
        float xv = buf[t & 7];
        if (t + 8 < TT) buf[t & 7] = yp[(size_t)(t + 8) * ROWSTRIDE];
        float yn = fmaf(xv, sc, sh);
        v = 0.5f * (v + yn);
        float s = (v >= 1.f) ? 1.f : 0.f;
        sp[(size_t)t * ROWSTRIDE] = __float2half(s);
        cnt += s;
        v = (v >= 1.f) ? 0.f : v;
    }
    if (write_rate) g_rate[b * 256 + e] = cnt * (1.f / TT);
}

// ---------------- head ----------------------------------------------------------
__global__ void head_k(const float* __restrict__ hw, const float* __restrict__ hb,
                       float* __restrict__ out) {
    __shared__ float rs[EE];
    int b = blockIdx.x, tid = threadIdx.x;   // 64 threads
    for (int j = tid; j < EE; j += 64) rs[j] = g_rate[b * EE + j];
    __syncthreads();
    if (tid < OUTD) {
        float acc = hb[tid];
#pragma unroll 8
        for (int e2 = 0; e2 < EE; e2++) acc += rs[e2] * hw[tid * EE + e2];
        out[b * OUTD + tid] = acc;
    }
}

// ---------------- launch ---------------------------------------------------------
extern "C" void kernel_launch(void* const* d_in, const int* in_sizes, int n_in,
                              void* d_out, int out_size) {
    const float *x = 0, *conv0_w = 0, *conv0_b = 0, *convs_w = 0, *convs_b = 0;
    const float *gamma = 0, *beta = 0, *head_w = 0, *head_b = 0;
    int n1024_seen = 0;
    int alphabetical = (n_in > 0 && in_sizes[0] == 1024);
    for (int i = 0; i < n_in; i++) {
        const float* p = (const float*)d_in[i];
        switch (in_sizes[i]) {
            case 524288: x = p; break;
            case 6144:   conv0_w = p; break;
            case 256:    conv0_b = p; break;
            case 589824: convs_w = p; break;
            case 768:    convs_b = p; break;
            case 16128:  head_w = p; break;
            case 63:     head_b = p; break;
            case 1024:
                if (n1024_seen == 0) { if (alphabetical) beta = p; else gamma = p; }
                else                 { if (alphabetical) gamma = p; else beta = p; }
                n1024_seen++;
                break;
            default: break;
        }
    }
    float* out = (float*)d_out;

    cudaFuncSetAttribute(conv_mma_k, cudaFuncAttributeMaxDynamicSharedMemorySize, SMEM_BYTES);

    repack_wh_k<<<(3 * 768 * 256 + 255) / 256, 256>>>(convs_w);
    prep_k<<<(2 * ROWSTRIDE + 255) / 256, 256>>>(conv0_w);

    // block 0
    conv0_k<<<TT, 256>>>(x, conv0_b);
    stats1_k<<<256, 256>>>();
    stats2_k<<<256, 128>>>(256);
    lif_k<<<BB * 4, 64>>>(gamma + 0 * EE, beta + 0 * EE, 0);

    // blocks 1..3 (fp16 scaled-2-split GEMM, fused stats, parallel finalize)
    for (int i = 0; i < 3; i++) {
        conv_mma_k<<<dim3(2, 512), 512, SMEM_BYTES>>>(i, convs_b + i * EE);
        stats2_k<<<256, 128>>>(512);
        lif_k<<<BB * 4, 64>>>(gamma + (i + 1) * EE, beta + (i + 1) * EE, (i == 2) ? 1 : 0);
    }

    head_k<<<BB, 64>>>(head_w, head_b, out);
}

// round 10
// speedup vs baseline: 4.8988x; 1.1613x over previous
#include <cuda_runtime.h>
#include <cuda_fp16.h>
#include <cstdint>

#define BB 64
#define TT 1024
#define EE 256
#define CIN 8
#define OUTD 63
#define NROW (BB*TT)          // 65536
#define ROWSTRIDE (BB*EE)     // 16384

#define LO_SCALE 4096.f
#define LO_INV   (1.f/4096.f)

// ---------------- scratch ----------------------------------------------------
__device__ float g_y[NROW * EE];                                // conv out [(t*B+b)][e]
__device__ __align__(16) __half g_spad[(TT + 2) * ROWSTRIDE];   // fp16 spikes, t-padded
__device__ __align__(16) __half g_wh[3 * 2 * 768 * 256];        // fp16 weights [layer][split][k][n]
__device__ float g_w0[3 * CIN * EE];
__device__ float g_psum[EE * 1024];                             // TRANSPOSED: [e][row]
__device__ float g_psq[EE * 1024];
__device__ float g_sum[EE];
__device__ float g_sq[EE];
__device__ float g_rate[BB * EE];

// ---------------- ptx helpers ------------------------------------------------
__device__ __forceinline__ uint32_t smem_u32(const void* p) {
    uint32_t a;
    asm("{ .reg .u64 t; cvta.to.shared.u64 t, %1; cvt.u32.u64 %0, t; }" : "=r"(a) : "l"(p));
    return a;
}
__device__ __forceinline__ void ldm4(uint32_t* r, uint32_t a) {
    asm volatile("ldmatrix.sync.aligned.m8n8.x4.shared.b16 {%0,%1,%2,%3}, [%4];"
                 : "=r"(r[0]), "=r"(r[1]), "=r"(r[2]), "=r"(r[3]) : "r"(a));
}
__device__ __forceinline__ void ldm4t(uint32_t* r, uint32_t a) {
    asm volatile("ldmatrix.sync.aligned.m8n8.x4.trans.shared.b16 {%0,%1,%2,%3}, [%4];"
                 : "=r"(r[0]), "=r"(r[1]), "=r"(r[2]), "=r"(r[3]) : "r"(a));
}
__device__ __forceinline__ void mma_h(float* d, const uint32_t* a, const uint32_t* b) {
    asm volatile("mma.sync.aligned.m16n8k16.row.col.f32.f16.f16.f32 "
                 "{%0,%1,%2,%3}, {%4,%5,%6,%7}, {%8,%9}, {%0,%1,%2,%3};"
                 : "+f"(d[0]), "+f"(d[1]), "+f"(d[2]), "+f"(d[3])
                 : "r"(a[0]), "r"(a[1]), "r"(a[2]), "r"(a[3]), "r"(b[0]), "r"(b[1]));
}
__device__ __forceinline__ void cpa16(uint32_t dst, const void* src) {
    asm volatile("cp.async.cg.shared.global [%0], [%1], 16;" :: "r"(dst), "l"(src));
}
#define CPA_COMMIT() asm volatile("cp.async.commit_group;" ::: "memory")
#define CPA_WAIT2()  asm volatile("cp.async.wait_group 2;" ::: "memory")

// ---------------- prep kernels -----------------------------------------------
__global__ void repack_wh_k(const float* __restrict__ w) {
    int idx = blockIdx.x * blockDim.x + threadIdx.x;     // 3*768*256
    if (idx >= 3 * 768 * 256) return;
    int n = idx & 255;
    int k = (idx >> 8) % 768;          // k = kpos*256 + c
    int i = idx / (768 * 256);
    int kpos = k >> 8;
    int c = k & 255;
    float wf = w[((i * 256 + n) * 256 + c) * 3 + kpos];
    __half h0 = __float2half_rn(wf);
    float lo = (wf - __half2float(h0)) * LO_SCALE;
    __half h1 = __float2half_rn(lo);
    g_wh[((size_t)(i * 2 + 0) * 768 + k) * 256 + n] = h0;
    g_wh[((size_t)(i * 2 + 1) * 768 + k) * 256 + n] = h1;
}

// merged: conv0 weight repack + spad time-pad zeroing
__global__ void prep_k(const float* __restrict__ w0) {
    int idx = blockIdx.x * blockDim.x + threadIdx.x;
    if (idx < ROWSTRIDE) g_spad[idx] = __float2half(0.f);
    else if (idx < 2 * ROWSTRIDE) g_spad[(TT + 1) * ROWSTRIDE + (idx - ROWSTRIDE)] = __float2half(0.f);
    if (idx < 3 * CIN * 256) {
        int o = idx & 255;
        int c = (idx >> 8) & 7;
        int k = idx >> 11;
        g_w0[idx] = w0[(o * CIN + c) * 3 + k];
    }
}

// ---------------- conv0: one CTA per t, weights in regs, fused stats -----------
__global__ void __launch_bounds__(256) conv0_k(const float* __restrict__ x,
                                               const float* __restrict__ bias) {
    __shared__ float xs[64][24];
    int t = blockIdx.x;
    int tid = threadIdx.x;
    float wr[24];
#pragma unroll
    for (int j = 0; j < 24; j++) wr[j] = g_w0[j * 256 + tid];
    for (int q = tid; q < 64 * 24; q += 256) {
        int bl = q / 24, rem = q % 24;
        int k = rem >> 3, c = rem & 7;
        int ttm = t - 1 + k;
        float v = 0.f;
        if (ttm >= 0 && ttm < TT) v = x[((bl) * TT + ttm) * CIN + c];
        xs[bl][rem] = v;
    }
    __syncthreads();
    float bo = bias[tid];
    float s = 0.f, qq = 0.f;
#pragma unroll 2
    for (int r = 0; r < 64; r++) {
        float acc = bo;
#pragma unroll
        for (int j = 0; j < 24; j++) acc += wr[j] * xs[r][j];
        g_y[(size_t)(t * BB + r) * EE + tid] = acc;
        s += acc;
        qq += acc * acc;
    }
    g_psum[(size_t)tid * 1024 + t] = s;
    g_psq[(size_t)tid * 1024 + t] = qq;
}

// ---------------- fp16 scaled-2-split MMA conv GEMM (512 thr, cp.async x4) ------
#define APITCH 40
#define BPITCH 136
#define A_H 5120
#define B_SP 4352
#define ST_H (A_H + 2 * B_SP)
#define NSTAGE 4
#define SMEM_HALVES (NSTAGE * ST_H)
#define SMEM_BYTES (SMEM_HALVES * 2)

__global__ void __launch_bounds__(512, 1) conv_mma_k(int layer, const float* __restrict__ bias) {
    extern __shared__ __half sm[];
    const int tid = threadIdx.x;
    const int lane = tid & 31;
    const int wid = tid >> 5;
    const int wm = wid & 3;
    const int wn = wid >> 2;
    const int mt = blockIdx.y;
    const int nb = blockIdx.x;

    const uint4* __restrict__ wsrc = (const uint4*)(g_wh + (size_t)layer * 2 * 768 * 256);

    float acch[2][4][4], accl[2][4][4];
#pragma unroll
    for (int mi = 0; mi < 2; mi++)
#pragma unroll
        for (int u = 0; u < 4; u++)
#pragma unroll
            for (int q = 0; q < 4; q++) { acch[mi][u][q] = 0.f; accl[mi][u][q] = 0.f; }

    const int arow = tid >> 2;
    const int aq = tid & 3;
    const uint32_t smb = smem_u32(sm);

    auto issue = [&](int ck, int st) {
        int kpos = ck >> 3, c0 = (ck & 7) << 5;
        uint32_t base = smb + (uint32_t)(st * ST_H) * 2;
        cpa16(base + (arow * APITCH + aq * 8) * 2,
              g_spad + (size_t)(2 * mt + (arow >> 6) + kpos) * ROWSTRIDE + (arow & 63) * 256 + c0 + aq * 8);
#pragma unroll
        for (int it = 0; it < 2; it++) {
            int u = tid + it * 512;
            int s = u >> 9, rest = u & 511;
            int kk = rest >> 4, g = rest & 15;
            cpa16(base + (A_H + s * B_SP + kk * BPITCH + g * 8) * 2,
                  wsrc + (size_t)(s * 768 + kpos * 256 + c0 + kk) * 32 + nb * 16 + g);
        }
    };

#pragma unroll
    for (int p = 0; p < 3; p++) { issue(p, p); CPA_COMMIT(); }

    for (int ck = 0; ck < 24; ck++) {
        CPA_WAIT2();
        __syncthreads();
        if (ck + 3 < 24) issue(ck + 3, (ck + 3) & 3);
        CPA_COMMIT();

        const __half* Asm = sm + (ck & 3) * ST_H;
        const __half* Bsm = Asm + A_H;
#pragma unroll
        for (int kh = 0; kh < 2; kh++) {
            uint32_t afr[2][4];
#pragma unroll
            for (int mi = 0; mi < 2; mi++) {
                uint32_t ad = smem_u32(Asm + (wm * 32 + mi * 16 + (lane & 15)) * APITCH
                                       + kh * 16 + (lane >> 4) * 8);
                ldm4(afr[mi], ad);
            }
#pragma unroll
            for (int s = 0; s < 2; s++) {
                uint32_t bfr[2][4];
#pragma unroll
                for (int q = 0; q < 2; q++) {
                    uint32_t bd = smem_u32(Bsm + s * B_SP + (kh * 16 + (lane & 15)) * BPITCH
                                           + wn * 32 + q * 16 + (lane >> 4) * 8);
                    ldm4t(bfr[q], bd);
                }
                if (s == 0) {
#pragma unroll
                    for (int mi = 0; mi < 2; mi++)
#pragma unroll
                        for (int q = 0; q < 2; q++)
#pragma unroll
                            for (int h = 0; h < 2; h++)
                                mma_h(acch[mi][q * 2 + h], afr[mi], &bfr[q][h * 2]);
                } else {
#pragma unroll
                    for (int mi = 0; mi < 2; mi++)
#pragma unroll
                        for (int q = 0; q < 2; q++)
#pragma unroll
                            for (int h = 0; h < 2; h++)
                                mma_h(accl[mi][q * 2 + h], afr[mi], &bfr[q][h * 2]);
                }
            }
        }
    }

    // epilogue: combine splits, write y, fused column stats
    __syncthreads();
    float* red = (float*)sm;

    const int m0 = mt * 128 + wm * 32 + (lane >> 2);
    float csum[8], csq[8];
#pragma unroll
    for (int j = 0; j < 8; j++) { csum[j] = 0.f; csq[j] = 0.f; }

#pragma unroll
    for (int u = 0; u < 4; u++) {
        int n = nb * 128 + wn * 32 + (u >> 1) * 16 + (u & 1) * 8 + (lane & 3) * 2;
        float2 bv = *(const float2*)(bias + n);
#pragma unroll
        for (int mi = 0; mi < 2; mi++) {
            int r0 = m0 + mi * 16;
            float v00 = fmaf(accl[mi][u][0], LO_INV, acch[mi][u][0]) + bv.x;
            float v01 = fmaf(accl[mi][u][1], LO_INV, acch[mi][u][1]) + bv.y;
            float v10 = fmaf(accl[mi][u][2], LO_INV, acch[mi][u][2]) + bv.x;
            float v11 = fmaf(accl[mi][u][3], LO_INV, acch[mi][u][3]) + bv.y;
            float2 w0, w1;
            w0.x = v00; w0.y = v01;
            w1.x = v10; w1.y = v11;
            *(float2*)(g_y + (size_t)r0 * 256 + n) = w0;
            *(float2*)(g_y + (size_t)(r0 + 8) * 256 + n) = w1;
            csum[u * 2 + 0] += v00 + v10;
            csum[u * 2 + 1] += v01 + v11;
            csq[u * 2 + 0] += v00 * v00 + v10 * v10;
            csq[u * 2 + 1] += v01 * v01 + v11 * v11;
        }
    }
#pragma unroll
    for (int off = 4; off < 32; off <<= 1)
#pragma unroll
        for (int j = 0; j < 8; j++) {
            csum[j] += __shfl_xor_sync(0xffffffffu, csum[j], off);
            csq[j]  += __shfl_xor_sync(0xffffffffu, csq[j],  off);
        }
    if (lane < 4) {
#pragma unroll
        for (int j = 0; j < 8; j++) {
            int u = j >> 1;
            int cl = wn * 32 + (u >> 1) * 16 + (u & 1) * 8 + lane * 2 + (j & 1);
            red[wm * 128 + cl] = csum[j];
            red[512 + wm * 128 + cl] = csq[j];
        }
    }
    __syncthreads();
    if (tid < 128) {
        float s = red[tid] + red[128 + tid] + red[256 + tid] + red[384 + tid];
        float q = red[512 + tid] + red[640 + tid] + red[768 + tid] + red[896 + tid];
        g_psum[(size_t)(nb * 128 + tid) * 1024 + mt] = s;
        g_psq[(size_t)(nb * 128 + tid) * 1024 + mt] = q;
    }
}

// ---------------- BN stats finalize: 1 block per channel ------------------------
__global__ void __launch_bounds__(128) stats2_k(int nrows) {
    __shared__ float ss[128], qq[128];
    int e = blockIdx.x;
    int t = threadIdx.x;
    const float* ps = g_psum + (size_t)e * 1024;
    const float* pq = g_psq + (size_t)e * 1024;
    float s = 0.f, q = 0.f;
    for (int r = t; r < nrows; r += 128) { s += ps[r]; q += pq[r]; }
    ss[t] = s; qq[t] = q;
    __syncthreads();
#pragma unroll
    for (int off = 64; off > 0; off >>= 1) {
        if (t < off) { ss[t] += ss[t + off]; qq[t] += qq[t + off]; }
        __syncthreads();
    }
    if (t == 0) { g_sum[e] = ss[0]; g_sq[e] = qq[0]; }
}

// ---------------- BN apply + LIF (prefetch depth 16) ----------------------------
__global__ void lif_k(const float* __restrict__ gamma, const float* __restrict__ beta,
                      int write_rate) {
    int b = blockIdx.x >> 2;
    int e = ((blockIdx.x & 3) << 6) + threadIdx.x;   // blockDim = 64
    float mu = g_sum[e] * (1.f / NROW);
    float var = g_sq[e] * (1.f / NROW) - mu * mu;
    float sc = gamma[e] / sqrtf(var + 1e-5f);
    float sh = fmaf(-mu, sc, beta[e]);

    const float* yp = g_y + b * 256 + e;
    __half* sp = g_spad + ROWSTRIDE + b * 256 + e;

    float buf[16];
#pragma unroll
    for (int i = 0; i < 16; i++) buf[i] = yp[(size_t)i * ROWSTRIDE];
    float v = 0.f, cnt = 0.f;
#pragma unroll 16
    for (int t = 0; t < TT; t++) {
        float xv = buf[t & 15];
        if (t + 16 < TT) buf[t & 15] = yp[(size_t)(t + 16) * ROWSTRIDE];
        float yn = fmaf(xv, sc, sh);
        v = 0.5f * (v + yn);
        float s = (v >= 1.f) ? 1.f : 0.f;
        sp[(size_t)t * ROWSTRIDE] = __float2half(s);
        cnt += s;
        v = (v >= 1.f) ? 0.f : v;
    }
    if (write_rate) g_rate[b * 256 + e] = cnt * (1.f / TT);
}

// ---------------- head ----------------------------------------------------------
__global__ void head_k(const float* __restrict__ hw, const float* __restrict__ hb,
                       float* __restrict__ out) {
    __shared__ float rs[EE];
    int b = blockIdx.x, tid = threadIdx.x;   // 64 threads
    for (int j = tid; j < EE; j += 64) rs[j] = g_rate[b * EE + j];
    __syncthreads();
    if (tid < OUTD) {
        float acc = hb[tid];
#pragma unroll 8
        for (int e2 = 0; e2 < EE; e2++) acc += rs[e2] * hw[tid * EE + e2];
        out[b * OUTD + tid] = acc;
    }
}

// ---------------- launch ---------------------------------------------------------
extern "C" void kernel_launch(void* const* d_in, const int* in_sizes, int n_in,
                              void* d_out, int out_size) {
    const float *x = 0, *conv0_w = 0, *conv0_b = 0, *convs_w = 0, *convs_b = 0;
    const float *gamma = 0, *beta = 0, *head_w = 0, *head_b = 0;
    int n1024_seen = 0;
    int alphabetical = (n_in > 0 && in_sizes[0] == 1024);
    for (int i = 0; i < n_in; i++) {
        const float* p = (const float*)d_in[i];
        switch (in_sizes[i]) {
            case 524288: x = p; break;
            case 6144:   conv0_w = p; break;
            case 256:    conv0_b = p; break;
            case 589824: convs_w = p; break;
            case 768:    convs_b = p; break;
            case 16128:  head_w = p; break;
            case 63:     head_b = p; break;
            case 1024:
                if (n1024_seen == 0) { if (alphabetical) beta = p; else gamma = p; }
                else                 { if (alphabetical) gamma = p; else beta = p; }
                n1024_seen++;
                break;
            default: break;
        }
    }
    float* out = (float*)d_out;

    cudaFuncSetAttribute(conv_mma_k, cudaFuncAttributeMaxDynamicSharedMemorySize, SMEM_BYTES);

    repack_wh_k<<<(3 * 768 * 256 + 255) / 256, 256>>>(convs_w);
    prep_k<<<(2 * ROWSTRIDE + 255) / 256, 256>>>(conv0_w);

    // block 0 (stats fused into conv0)
    conv0_k<<<TT, 256>>>(x, conv0_b);
    stats2_k<<<256, 128>>>(1024);
    lif_k<<<BB * 4, 64>>>(gamma + 0 * EE, beta + 0 * EE, 0);

    // blocks 1..3
    for (int i = 0; i < 3; i++) {
        conv_mma_k<<<dim3(2, 512), 512, SMEM_BYTES>>>(i, convs_b + i * EE);
        stats2_k<<<256, 128>>>(512);
        lif_k<<<BB * 4, 64>>>(gamma + (i + 1) * EE, beta + (i + 1) * EE, (i == 2) ? 1 : 0);
    }

    head_k<<<BB, 64>>>(head_w, head_b, out);
}

// round 12
// speedup vs baseline: 5.0676x; 1.0345x over previous
#include <cuda_runtime.h>
#include <cuda_fp16.h>
#include <cstdint>

#define BB 64
#define TT 1024
#define EE 256
#define CIN 8
#define OUTD 63
#define NROW (BB*TT)          // 65536
#define ROWSTRIDE (BB*EE)     // 16384

#define LO_SCALE 4096.f
#define LO_INV   (1.f/4096.f)

// ---------------- scratch ----------------------------------------------------
__device__ float g_y[NROW * EE];                                // conv out [(t*B+b)][e]
__device__ __align__(16) __half g_spad[(TT + 2) * ROWSTRIDE];   // fp16 spikes, t-padded
__device__ __align__(16) __half g_wh[3 * 2 * 768 * 256];        // fp16 weights [layer][split][k][n]
__device__ float g_w0[3 * CIN * EE];
__device__ float g_psum[EE * 1024];                             // TRANSPOSED: [e][row]
__device__ float g_psq[EE * 1024];
__device__ float g_sum[EE];
__device__ float g_sq[EE];
__device__ float g_rate[BB * EE];

// ---------------- ptx helpers ------------------------------------------------
__device__ __forceinline__ uint32_t smem_u32(const void* p) {
    uint32_t a;
    asm("{ .reg .u64 t; cvta.to.shared.u64 t, %1; cvt.u32.u64 %0, t; }" : "=r"(a) : "l"(p));
    return a;
}
__device__ __forceinline__ void ldm4(uint32_t* r, uint32_t a) {
    asm volatile("ldmatrix.sync.aligned.m8n8.x4.shared.b16 {%0,%1,%2,%3}, [%4];"
                 : "=r"(r[0]), "=r"(r[1]), "=r"(r[2]), "=r"(r[3]) : "r"(a));
}
__device__ __forceinline__ void ldm4t(uint32_t* r, uint32_t a) {
    asm volatile("ldmatrix.sync.aligned.m8n8.x4.trans.shared.b16 {%0,%1,%2,%3}, [%4];"
                 : "=r"(r[0]), "=r"(r[1]), "=r"(r[2]), "=r"(r[3]) : "r"(a));
}
__device__ __forceinline__ void mma_h(float* d, const uint32_t* a, const uint32_t* b) {
    asm volatile("mma.sync.aligned.m16n8k16.row.col.f32.f16.f16.f32 "
                 "{%0,%1,%2,%3}, {%4,%5,%6,%7}, {%8,%9}, {%0,%1,%2,%3};"
                 : "+f"(d[0]), "+f"(d[1]), "+f"(d[2]), "+f"(d[3])
                 : "r"(a[0]), "r"(a[1]), "r"(a[2]), "r"(a[3]), "r"(b[0]), "r"(b[1]));
}
__device__ __forceinline__ void cpa16(uint32_t dst, const void* src) {
    asm volatile("cp.async.cg.shared.global [%0], [%1], 16;" :: "r"(dst), "l"(src));
}
#define CPA_COMMIT() asm volatile("cp.async.commit_group;" ::: "memory")
#define CPA_WAIT2()  asm volatile("cp.async.wait_group 2;" ::: "memory")

// ---------------- prep kernels -----------------------------------------------
__global__ void repack_wh_k(const float* __restrict__ w) {
    int idx = blockIdx.x * blockDim.x + threadIdx.x;     // 3*768*256
    if (idx >= 3 * 768 * 256) return;
    int n = idx & 255;
    int k = (idx >> 8) % 768;          // k = kpos*256 + c
    int i = idx / (768 * 256);
    int kpos = k >> 8;
    int c = k & 255;
    float wf = w[((i * 256 + n) * 256 + c) * 3 + kpos];
    __half h0 = __float2half_rn(wf);
    float lo = (wf - __half2float(h0)) * LO_SCALE;
    __half h1 = __float2half_rn(lo);
    g_wh[((size_t)(i * 2 + 0) * 768 + k) * 256 + n] = h0;
    g_wh[((size_t)(i * 2 + 1) * 768 + k) * 256 + n] = h1;
}

// merged: conv0 weight repack + spad time-pad zeroing
__global__ void prep_k(const float* __restrict__ w0) {
    int idx = blockIdx.x * blockDim.x + threadIdx.x;
    if (idx < ROWSTRIDE) g_spad[idx] = __float2half(0.f);
    else if (idx < 2 * ROWSTRIDE) g_spad[(TT + 1) * ROWSTRIDE + (idx - ROWSTRIDE)] = __float2half(0.f);
    if (idx < 3 * CIN * 256) {
        int o = idx & 255;
        int c = (idx >> 8) & 7;
        int k = idx >> 11;
        g_w0[idx] = w0[(o * CIN + c) * 3 + k];
    }
}

// ---------------- conv0: one CTA per t, weights in regs, fused stats -----------
__global__ void __launch_bounds__(256) conv0_k(const float* __restrict__ x,
                                               const float* __restrict__ bias) {
    __shared__ float xs[64][24];
    int t = blockIdx.x;
    int tid = threadIdx.x;
    float wr[24];
#pragma unroll
    for (int j = 0; j < 24; j++) wr[j] = g_w0[j * 256 + tid];
    for (int q = tid; q < 64 * 24; q += 256) {
        int bl = q / 24, rem = q % 24;
        int k = rem >> 3, c = rem & 7;
        int ttm = t - 1 + k;
        float v = 0.f;
        if (ttm >= 0 && ttm < TT) v = x[((bl) * TT + ttm) * CIN + c];
        xs[bl][rem] = v;
    }
    __syncthreads();
    float bo = bias[tid];
    float s = 0.f, qq = 0.f;
#pragma unroll 2
    for (int r = 0; r < 64; r++) {
        float acc = bo;
#pragma unroll
        for (int j = 0; j < 24; j++) acc += wr[j] * xs[r][j];
        g_y[(size_t)(t * BB + r) * EE + tid] = acc;
        s += acc;
        qq += acc * acc;
    }
    g_psum[(size_t)tid * 1024 + t] = s;
    g_psq[(size_t)tid * 1024 + t] = qq;
}

// ---------------- fp16 scaled-2-split MMA conv GEMM (512 thr, cp.async x4) ------
#define APITCH 40
#define BPITCH 136
#define A_H 5120
#define B_SP 4352
#define ST_H (A_H + 2 * B_SP)
#define NSTAGE 4
#define SMEM_HALVES (NSTAGE * ST_H)
#define SMEM_BYTES (SMEM_HALVES * 2)

__global__ void __launch_bounds__(512, 1) conv_mma_k(int layer, const float* __restrict__ bias) {
    extern __shared__ __half sm[];
    const int tid = threadIdx.x;
    const int lane = tid & 31;
    const int wid = tid >> 5;
    const int wm = wid & 3;
    const int wn = wid >> 2;
    const int mt = blockIdx.y;
    const int nb = blockIdx.x;

    const uint4* __restrict__ wsrc = (const uint4*)(g_wh + (size_t)layer * 2 * 768 * 256);

    float acch[2][4][4], accl[2][4][4];
#pragma unroll
    for (int mi = 0; mi < 2; mi++)
#pragma unroll
        for (int u = 0; u < 4; u++)
#pragma unroll
            for (int q = 0; q < 4; q++) { acch[mi][u][q] = 0.f; accl[mi][u][q] = 0.f; }

    const int arow = tid >> 2;
    const int aq = tid & 3;
    const uint32_t smb = smem_u32(sm);

    auto issue = [&](int ck, int st) {
        int kpos = ck >> 3, c0 = (ck & 7) << 5;
        uint32_t base = smb + (uint32_t)(st * ST_H) * 2;
        cpa16(base + (arow * APITCH + aq * 8) * 2,
              g_spad + (size_t)(2 * mt + (arow >> 6) + kpos) * ROWSTRIDE + (arow & 63) * 256 + c0 + aq * 8);
#pragma unroll
        for (int it = 0; it < 2; it++) {
            int u = tid + it * 512;
            int s = u >> 9, rest = u & 511;
            int kk = rest >> 4, g = rest & 15;
            cpa16(base + (A_H + s * B_SP + kk * BPITCH + g * 8) * 2,
                  wsrc + (size_t)(s * 768 + kpos * 256 + c0 + kk) * 32 + nb * 16 + g);
        }
    };

#pragma unroll
    for (int p = 0; p < 3; p++) { issue(p, p); CPA_COMMIT(); }

    for (int ck = 0; ck < 24; ck++) {
        CPA_WAIT2();
        __syncthreads();
        if (ck + 3 < 24) issue(ck + 3, (ck + 3) & 3);
        CPA_COMMIT();

        const __half* Asm = sm + (ck & 3) * ST_H;
        const __half* Bsm = Asm + A_H;
#pragma unroll
        for (int kh = 0; kh < 2; kh++) {
            uint32_t afr[2][4];
#pragma unroll
            for (int mi = 0; mi < 2; mi++) {
                uint32_t ad = smem_u32(Asm + (wm * 32 + mi * 16 + (lane & 15)) * APITCH
                                       + kh * 16 + (lane >> 4) * 8);
                ldm4(afr[mi], ad);
            }
#pragma unroll
            for (int s = 0; s < 2; s++) {
                uint32_t bfr[2][4];
#pragma unroll
                for (int q = 0; q < 2; q++) {
                    uint32_t bd = smem_u32(Bsm + s * B_SP + (kh * 16 + (lane & 15)) * BPITCH
                                           + wn * 32 + q * 16 + (lane >> 4) * 8);
                    ldm4t(bfr[q], bd);
                }
                if (s == 0) {
#pragma unroll
                    for (int mi = 0; mi < 2; mi++)
#pragma unroll
                        for (int q = 0; q < 2; q++)
#pragma unroll
                            for (int h = 0; h < 2; h++)
                                mma_h(acch[mi][q * 2 + h], afr[mi], &bfr[q][h * 2]);
                } else {
#pragma unroll
                    for (int mi = 0; mi < 2; mi++)
#pragma unroll
                        for (int q = 0; q < 2; q++)
#pragma unroll
                            for (int h = 0; h < 2; h++)
                                mma_h(accl[mi][q * 2 + h], afr[mi], &bfr[q][h * 2]);
                }
            }
        }
    }

    // epilogue: combine splits, write y, fused column stats
    __syncthreads();
    float* red = (float*)sm;

    const int m0 = mt * 128 + wm * 32 + (lane >> 2);
    float csum[8], csq[8];
#pragma unroll
    for (int j = 0; j < 8; j++) { csum[j] = 0.f; csq[j] = 0.f; }

#pragma unroll
    for (int u = 0; u < 4; u++) {
        int n = nb * 128 + wn * 32 + (u >> 1) * 16 + (u & 1) * 8 + (lane & 3) * 2;
        float2 bv = *(const float2*)(bias + n);
#pragma unroll
        for (int mi = 0; mi < 2; mi++) {
            int r0 = m0 + mi * 16;
            float v00 = fmaf(accl[mi][u][0], LO_INV, acch[mi][u][0]) + bv.x;
            float v01 = fmaf(accl[mi][u][1], LO_INV, acch[mi][u][1]) + bv.y;
            float v10 = fmaf(accl[mi][u][2], LO_INV, acch[mi][u][2]) + bv.x;
            float v11 = fmaf(accl[mi][u][3], LO_INV, acch[mi][u][3]) + bv.y;
            float2 w0, w1;
            w0.x = v00; w0.y = v01;
            w1.x = v10; w1.y = v11;
            *(float2*)(g_y + (size_t)r0 * 256 + n) = w0;
            *(float2*)(g_y + (size_t)(r0 + 8) * 256 + n) = w1;
            csum[u * 2 + 0] += v00 + v10;
            csum[u * 2 + 1] += v01 + v11;
            csq[u * 2 + 0] += v00 * v00 + v10 * v10;
            csq[u * 2 + 1] += v01 * v01 + v11 * v11;
        }
    }
#pragma unroll
    for (int off = 4; off < 32; off <<= 1)
#pragma unroll
        for (int j = 0; j < 8; j++) {
            csum[j] += __shfl_xor_sync(0xffffffffu, csum[j], off);
            csq[j]  += __shfl_xor_sync(0xffffffffu, csq[j],  off);
        }
    if (lane < 4) {
#pragma unroll
        for (int j = 0; j < 8; j++) {
            int u = j >> 1;
            int cl = wn * 32 + (u >> 1) * 16 + (u & 1) * 8 + lane * 2 + (j & 1);
            red[wm * 128 + cl] = csum[j];
            red[512 + wm * 128 + cl] = csq[j];
        }
    }
    __syncthreads();
    if (tid < 128) {
        float s = red[tid] + red[128 + tid] + red[256 + tid] + red[384 + tid];
        float q = red[512 + tid] + red[640 + tid] + red[768 + tid] + red[896 + tid];
        g_psum[(size_t)(nb * 128 + tid) * 1024 + mt] = s;
        g_psq[(size_t)(nb * 128 + tid) * 1024 + mt] = q;
    }
}

// ---------------- BN stats finalize: 1 block per channel ------------------------
__global__ void __launch_bounds__(128) stats2_k(int nrows) {
    __shared__ float ss[128], qq[128];
    int e = blockIdx.x;
    int t = threadIdx.x;
    const float* ps = g_psum + (size_t)e * 1024;
    const float* pq = g_psq + (size_t)e * 1024;
    float s = 0.f, q = 0.f;
    for (int r = t; r < nrows; r += 128) { s += ps[r]; q += pq[r]; }
    ss[t] = s; qq[t] = q;
    __syncthreads();
#pragma unroll
    for (int off = 64; off > 0; off >>= 1) {
        if (t < off) { ss[t] += ss[t + off]; qq[t] += qq[t + off]; }
        __syncthreads();
    }
    if (t == 0) { g_sum[e] = ss[0]; g_sq[e] = qq[0]; }
}

// ---------------- BN apply + LIF (prefetch depth 32) ----------------------------
__global__ void lif_k(const float* __restrict__ gamma, const float* __restrict__ beta,
                      int write_rate) {
    int b = blockIdx.x >> 2;
    int e = ((blockIdx.x & 3) << 6) + threadIdx.x;   // blockDim = 64
    float mu = g_sum[e] * (1.f / NROW);
    float var = g_sq[e] * (1.f / NROW) - mu * mu;
    float sc = gamma[e] / sqrtf(var + 1e-5f);
    float sh = fmaf(-mu, sc, beta[e]);

    const float* yp = g_y + b * 256 + e;
    __half* sp = g_spad + ROWSTRIDE + b * 256 + e;

    float buf[32];
#pragma unroll
    for (int i = 0; i < 32; i++) buf[i] = yp[(size_t)i * ROWSTRIDE];
    float v = 0.f, cnt = 0.f;
    if (write_rate) {
        // last layer: spikes never consumed, only the rate
#pragma unroll 32
        for (int t = 0; t < TT; t++) {
            float xv = buf[t & 31];
            if (t + 32 < TT) buf[t & 31] = yp[(size_t)(t + 32) * ROWSTRIDE];
            float yn = fmaf(xv, sc, sh);
            v = 0.5f * (v + yn);
            float s = (v >= 1.f) ? 1.f : 0.f;
            cnt += s;
            v = (v >= 1.f) ? 0.f : v;
        }
        g_rate[b * 256 + e] = cnt * (1.f / TT);
    } else {
#pragma unroll 32
        for (int t = 0; t < TT; t++) {
            float xv = buf[t & 31];
            if (t + 32 < TT) buf[t & 31] = yp[(size_t)(t + 32) * ROWSTRIDE];
            float yn = fmaf(xv, sc, sh);
            v = 0.5f * (v + yn);
            float s = (v >= 1.f) ? 1.f : 0.f;
            sp[(size_t)t * ROWSTRIDE] = __float2half(s);
            v = (v >= 1.f) ? 0.f : v;
        }
    }
}

// ---------------- head ----------------------------------------------------------
__global__ void head_k(const float* __restrict__ hw, const float* __restrict__ hb,
                       float* __restrict__ out) {
    __shared__ float rs[EE];
    int b = blockIdx.x, tid = threadIdx.x;   // 64 threads
    for (int j = tid; j < EE; j += 64) rs[j] = g_rate[b * EE + j];
    __syncthreads();
    if (tid < OUTD) {
        float acc = hb[tid];
#pragma unroll 8
        for (int e2 = 0; e2 < EE; e2++) acc += rs[e2] * hw[tid * EE + e2];
        out[b * OUTD + tid] = acc;
    }
}

// ---------------- launch ---------------------------------------------------------
extern "C" void kernel_launch(void* const* d_in, const int* in_sizes, int n_in,
                              void* d_out, int out_size) {
    const float *x = 0, *conv0_w = 0, *conv0_b = 0, *convs_w = 0, *convs_b = 0;
    const float *gamma = 0, *beta = 0, *head_w = 0, *head_b = 0;
    int n1024_seen = 0;
    int alphabetical = (n_in > 0 && in_sizes[0] == 1024);
    for (int i = 0; i < n_in; i++) {
        const float* p = (const float*)d_in[i];
        switch (in_sizes[i]) {
            case 524288: x = p; break;
            case 6144:   conv0_w = p; break;
            case 256:    conv0_b = p; break;
            case 589824: convs_w = p; break;
            case 768:    convs_b = p; break;
            case 16128:  head_w = p; break;
            case 63:     head_b = p; break;
            case 1024:
                if (n1024_seen == 0) { if (alphabetical) beta = p; else gamma = p; }
                else                 { if (alphabetical) gamma = p; else beta = p; }
                n1024_seen++;
                break;
            default: break;
        }
    }
    float* out = (float*)d_out;

    cudaFuncSetAttribute(conv_mma_k, cudaFuncAttributeMaxDynamicSharedMemorySize, SMEM_BYTES);

    // block 0 first; heavy weight repack deferred past the layer-0 chain head
    prep_k<<<(2 * ROWSTRIDE + 255) / 256, 256>>>(conv0_w);
    conv0_k<<<TT, 256>>>(x, conv0_b);
    stats2_k<<<256, 128>>>(1024);
    lif_k<<<BB * 4, 64>>>(gamma + 0 * EE, beta + 0 * EE, 0);

    repack_wh_k<<<(3 * 768 * 256 + 255) / 256, 256>>>(convs_w);

    // blocks 1..3 (fp16 scaled-2-split GEMM, fused stats, parallel finalize)
    for (int i = 0; i < 3; i++) {
        conv_mma_k<<<dim3(2, 512), 512, SMEM_BYTES>>>(i, convs_b + i * EE);
        stats2_k<<<256, 128>>>(512);
        lif_k<<<BB * 4, 64>>>(gamma + (i + 1) * EE, beta + (i + 1) * EE, (i == 2) ? 1 : 0);
    }

    head_k<<<BB, 64>>>(head_w, head_b, out);
}

// round 13
// speedup vs baseline: 5.7508x; 1.1348x over previous
#include <cuda_runtime.h>
#include <cuda_fp16.h>
#include <cstdint>

#define BB 64
#define TT 1024
#define EE 256
#define CIN 8
#define OUTD 63
#define NROW (BB*TT)          // 65536
#define ROWSTRIDE (BB*EE)     // 16384

#define LO_SCALE 4096.f
#define LO_INV   (1.f/4096.f)
#define LIF_WARM 160

// ---------------- scratch ----------------------------------------------------
__device__ float g_y[NROW * EE];                                // conv out [(t*B+b)][e]
__device__ __align__(16) __half g_spad[(TT + 2) * ROWSTRIDE];   // fp16 spikes, t-padded
__device__ __align__(16) __half g_wh[3 * 2 * 768 * 256];        // fp16 weights [layer][split][k][n]
__device__ float g_w0[3 * CIN * EE];
__device__ float g_psum[EE * 1024];                             // TRANSPOSED: [e][row]; also lif partial counts
__device__ float g_psq[EE * 1024];
__device__ float g_sum[EE];
__device__ float g_sq[EE];

// ---------------- ptx helpers ------------------------------------------------
__device__ __forceinline__ uint32_t smem_u32(const void* p) {
    uint32_t a;
    asm("{ .reg .u64 t; cvta.to.shared.u64 t, %1; cvt.u32.u64 %0, t; }" : "=r"(a) : "l"(p));
    return a;
}
__device__ __forceinline__ void ldm4(uint32_t* r, uint32_t a) {
    asm volatile("ldmatrix.sync.aligned.m8n8.x4.shared.b16 {%0,%1,%2,%3}, [%4];"
                 : "=r"(r[0]), "=r"(r[1]), "=r"(r[2]), "=r"(r[3]) : "r"(a));
}
__device__ __forceinline__ void ldm4t(uint32_t* r, uint32_t a) {
    asm volatile("ldmatrix.sync.aligned.m8n8.x4.trans.shared.b16 {%0,%1,%2,%3}, [%4];"
                 : "=r"(r[0]), "=r"(r[1]), "=r"(r[2]), "=r"(r[3]) : "r"(a));
}
__device__ __forceinline__ void mma_h(float* d, const uint32_t* a, const uint32_t* b) {
    asm volatile("mma.sync.aligned.m16n8k16.row.col.f32.f16.f16.f32 "
                 "{%0,%1,%2,%3}, {%4,%5,%6,%7}, {%8,%9}, {%0,%1,%2,%3};"
                 : "+f"(d[0]), "+f"(d[1]), "+f"(d[2]), "+f"(d[3])
                 : "r"(a[0]), "r"(a[1]), "r"(a[2]), "r"(a[3]), "r"(b[0]), "r"(b[1]));
}
__device__ __forceinline__ void cpa16(uint32_t dst, const void* src) {
    asm volatile("cp.async.cg.shared.global [%0], [%1], 16;" :: "r"(dst), "l"(src));
}
#define CPA_COMMIT() asm volatile("cp.async.commit_group;" ::: "memory")
#define CPA_WAIT2()  asm volatile("cp.async.wait_group 2;" ::: "memory")

// ---------------- prep kernels -----------------------------------------------
__global__ void repack_wh_k(const float* __restrict__ w) {
    int idx = blockIdx.x * blockDim.x + threadIdx.x;     // 3*768*256
    if (idx >= 3 * 768 * 256) return;
    int n = idx & 255;
    int k = (idx >> 8) % 768;          // k = kpos*256 + c
    int i = idx / (768 * 256);
    int kpos = k >> 8;
    int c = k & 255;
    float wf = w[((i * 256 + n) * 256 + c) * 3 + kpos];
    __half h0 = __float2half_rn(wf);
    float lo = (wf - __half2float(h0)) * LO_SCALE;
    __half h1 = __float2half_rn(lo);
    g_wh[((size_t)(i * 2 + 0) * 768 + k) * 256 + n] = h0;
    g_wh[((size_t)(i * 2 + 1) * 768 + k) * 256 + n] = h1;
}

// merged: conv0 weight repack + spad time-pad zeroing
__global__ void prep_k(const float* __restrict__ w0) {
    int idx = blockIdx.x * blockDim.x + threadIdx.x;
    if (idx < ROWSTRIDE) g_spad[idx] = __float2half(0.f);
    else if (idx < 2 * ROWSTRIDE) g_spad[(TT + 1) * ROWSTRIDE + (idx - ROWSTRIDE)] = __float2half(0.f);
    if (idx < 3 * CIN * 256) {
        int o = idx & 255;
        int c = (idx >> 8) & 7;
        int k = idx >> 11;
        g_w0[idx] = w0[(o * CIN + c) * 3 + k];
    }
}

// ---------------- conv0: one CTA per t, weights in regs, fused stats -----------
__global__ void __launch_bounds__(256) conv0_k(const float* __restrict__ x,
                                               const float* __restrict__ bias) {
    __shared__ float xs[64][24];
    int t = blockIdx.x;
    int tid = threadIdx.x;
    float wr[24];
#pragma unroll
    for (int j = 0; j < 24; j++) wr[j] = g_w0[j * 256 + tid];
    for (int q = tid; q < 64 * 24; q += 256) {
        int bl = q / 24, rem = q % 24;
        int k = rem >> 3, c = rem & 7;
        int ttm = t - 1 + k;
        float v = 0.f;
        if (ttm >= 0 && ttm < TT) v = x[((bl) * TT + ttm) * CIN + c];
        xs[bl][rem] = v;
    }
    __syncthreads();
    float bo = bias[tid];
    float s = 0.f, qq = 0.f;
#pragma unroll 2
    for (int r = 0; r < 64; r++) {
        float acc = bo;
#pragma unroll
        for (int j = 0; j < 24; j++) acc += wr[j] * xs[r][j];
        g_y[(size_t)(t * BB + r) * EE + tid] = acc;
        s += acc;
        qq += acc * acc;
    }
    g_psum[(size_t)tid * 1024 + t] = s;
    g_psq[(size_t)tid * 1024 + t] = qq;
}

// ---------------- fp16 scaled-2-split MMA conv GEMM (512 thr, cp.async x4) ------
#define APITCH 40
#define BPITCH 136
#define A_H 5120
#define B_SP 4352
#define ST_H (A_H + 2 * B_SP)
#define NSTAGE 4
#define SMEM_HALVES (NSTAGE * ST_H)
#define SMEM_BYTES (SMEM_HALVES * 2)

__global__ void __launch_bounds__(512, 1) conv_mma_k(int layer, const float* __restrict__ bias) {
    extern __shared__ __half sm[];
    const int tid = threadIdx.x;
    const int lane = tid & 31;
    const int wid = tid >> 5;
    const int wm = wid & 3;
    const int wn = wid >> 2;
    const int mt = blockIdx.y;
    const int nb = blockIdx.x;

    const uint4* __restrict__ wsrc = (const uint4*)(g_wh + (size_t)layer * 2 * 768 * 256);

    float acch[2][4][4], accl[2][4][4];
#pragma unroll
    for (int mi = 0; mi < 2; mi++)
#pragma unroll
        for (int u = 0; u < 4; u++)
#pragma unroll
            for (int q = 0; q < 4; q++) { acch[mi][u][q] = 0.f; accl[mi][u][q] = 0.f; }

    const int arow = tid >> 2;
    const int aq = tid & 3;
    const uint32_t smb = smem_u32(sm);

    auto issue = [&](int ck, int st) {
        int kpos = ck >> 3, c0 = (ck & 7) << 5;
        uint32_t base = smb + (uint32_t)(st * ST_H) * 2;
        cpa16(base + (arow * APITCH + aq * 8) * 2,
              g_spad + (size_t)(2 * mt + (arow >> 6) + kpos) * ROWSTRIDE + (arow & 63) * 256 + c0 + aq * 8);
#pragma unroll
        for (int it = 0; it < 2; it++) {
            int u = tid + it * 512;
            int s = u >> 9, rest = u & 511;
            int kk = rest >> 4, g = rest & 15;
            cpa16(base + (A_H + s * B_SP + kk * BPITCH + g * 8) * 2,
                  wsrc + (size_t)(s * 768 + kpos * 256 + c0 + kk) * 32 + nb * 16 + g);
        }
    };

#pragma unroll
    for (int p = 0; p < 3; p++) { issue(p, p); CPA_COMMIT(); }

    for (int ck = 0; ck < 24; ck++) {
        CPA_WAIT2();
        __syncthreads();
        if (ck + 3 < 24) issue(ck + 3, (ck + 3) & 3);
        CPA_COMMIT();

        const __half* Asm = sm + (ck & 3) * ST_H;
        const __half* Bsm = Asm + A_H;
#pragma unroll
        for (int kh = 0; kh < 2; kh++) {
            uint32_t afr[2][4];
#pragma unroll
            for (int mi = 0; mi < 2; mi++) {
                uint32_t ad = smem_u32(Asm + (wm * 32 + mi * 16 + (lane & 15)) * APITCH
                                       + kh * 16 + (lane >> 4) * 8);
                ldm4(afr[mi], ad);
            }
#pragma unroll
            for (int s = 0; s < 2; s++) {
                uint32_t bfr[2][4];
#pragma unroll
                for (int q = 0; q < 2; q++) {
                    uint32_t bd = smem_u32(Bsm + s * B_SP + (kh * 16 + (lane & 15)) * BPITCH
                                           + wn * 32 + q * 16 + (lane >> 4) * 8);
                    ldm4t(bfr[q], bd);
                }
                if (s == 0) {
#pragma unroll
                    for (int mi = 0; mi < 2; mi++)
#pragma unroll
                        for (int q = 0; q < 2; q++)
#pragma unroll
                            for (int h = 0; h < 2; h++)
                                mma_h(acch[mi][q * 2 + h], afr[mi], &bfr[q][h * 2]);
                } else {
#pragma unroll
                    for (int mi = 0; mi < 2; mi++)
#pragma unroll
                        for (int q = 0; q < 2; q++)
#pragma unroll
                            for (int h = 0; h < 2; h++)
                                mma_h(accl[mi][q * 2 + h], afr[mi], &bfr[q][h * 2]);
                }
            }
        }
    }

    // epilogue: combine splits, write y, fused column stats
    __syncthreads();
    float* red = (float*)sm;

    const int m0 = mt * 128 + wm * 32 + (lane >> 2);
    float csum[8], csq[8];
#pragma unroll
    for (int j = 0; j < 8; j++) { csum[j] = 0.f; csq[j] = 0.f; }

#pragma unroll
    for (int u = 0; u < 4; u++) {
        int n = nb * 128 + wn * 32 + (u >> 1) * 16 + (u & 1) * 8 + (lane & 3) * 2;
        float2 bv = *(const float2*)(bias + n);
#pragma unroll
        for (int mi = 0; mi < 2; mi++) {
            int r0 = m0 + mi * 16;
            float v00 = fmaf(accl[mi][u][0], LO_INV, acch[mi][u][0]) + bv.x;
            float v01 = fmaf(accl[mi][u][1], LO_INV, acch[mi][u][1]) + bv.y;
            float v10 = fmaf(accl[mi][u][2], LO_INV, acch[mi][u][2]) + bv.x;
            float v11 = fmaf(accl[mi][u][3], LO_INV, acch[mi][u][3]) + bv.y;
            float2 w0, w1;
            w0.x = v00; w0.y = v01;
            w1.x = v10; w1.y = v11;
            *(float2*)(g_y + (size_t)r0 * 256 + n) = w0;
            *(float2*)(g_y + (size_t)(r0 + 8) * 256 + n) = w1;
            csum[u * 2 + 0] += v00 + v10;
            csum[u * 2 + 1] += v01 + v11;
            csq[u * 2 + 0] += v00 * v00 + v10 * v10;
            csq[u * 2 + 1] += v01 * v01 + v11 * v11;
        }
    }
#pragma unroll
    for (int off = 4; off < 32; off <<= 1)
#pragma unroll
        for (int j = 0; j < 8; j++) {
            csum[j] += __shfl_xor_sync(0xffffffffu, csum[j], off);
            csq[j]  += __shfl_xor_sync(0xffffffffu, csq[j],  off);
        }
    if (lane < 4) {
#pragma unroll
        for (int j = 0; j < 8; j++) {
            int u = j >> 1;
            int cl = wn * 32 + (u >> 1) * 16 + (u & 1) * 8 + lane * 2 + (j & 1);
            red[wm * 128 + cl] = csum[j];
            red[512 + wm * 128 + cl] = csq[j];
        }
    }
    __syncthreads();
    if (tid < 128) {
        float s = red[tid] + red[128 + tid] + red[256 + tid] + red[384 + tid];
        float q = red[512 + tid] + red[640 + tid] + red[768 + tid] + red[896 + tid];
        g_psum[(size_t)(nb * 128 + tid) * 1024 + mt] = s;
        g_psq[(size_t)(nb * 128 + tid) * 1024 + mt] = q;
    }
}

// ---------------- BN stats finalize: 1 block per channel ------------------------
__global__ void __launch_bounds__(128) stats2_k(int nrows) {
    __shared__ float ss[128], qq[128];
    int e = blockIdx.x;
    int t = threadIdx.x;
    const float* ps = g_psum + (size_t)e * 1024;
    const float* pq = g_psq + (size_t)e * 1024;
    float s = 0.f, q = 0.f;
    for (int r = t; r < nrows; r += 128) { s += ps[r]; q += pq[r]; }
    ss[t] = s; qq[t] = q;
    __syncthreads();
#pragma unroll
    for (int off = 64; off > 0; off >>= 1) {
        if (t < off) { ss[t] += ss[t + off]; qq[t] += qq[t + off]; }
        __syncthreads();
    }
    if (t == 0) { g_sum[e] = ss[0]; g_sq[e] = qq[0]; }
}

// ---------------- BN apply + LIF, time-chunked with warmup collapse -------------
// grid = 4 chunks x 64 b x 4 e-quarters = 1024 blocks x 64 threads.
// Chunks 1-3 start v=0 at t0-LIF_WARM; hard reset collapses state exactly.
__global__ void __launch_bounds__(64) lif_k(const float* __restrict__ gamma,
                                            const float* __restrict__ beta,
                                            int write_rate) {
    int blk = blockIdx.x;
    int chunk = blk >> 8;                      // 0..3
    int r = blk & 255;
    int b = r >> 2;
    int e = ((r & 3) << 6) + threadIdx.x;
    float mu = g_sum[e] * (1.f / NROW);
    float var = g_sq[e] * (1.f / NROW) - mu * mu;
    float sc = gamma[e] / sqrtf(var + 1e-5f);
    float sh = fmaf(-mu, sc, beta[e]);

    const int t0 = chunk << 8;
    const int tw = (chunk == 0) ? 0 : (t0 - LIF_WARM);
    const int tend = t0 + 256;
    const float* yp = g_y + b * 256 + e;
    __half* sp = g_spad + (size_t)ROWSTRIDE + b * 256 + e;

    float buf[16];
#pragma unroll
    for (int i = 0; i < 16; i++) buf[i] = yp[(size_t)(tw + i) * ROWSTRIDE];
    float v = 0.f, cnt = 0.f;

    // warmup: no output; prefetch continues into the main window
#pragma unroll 16
    for (int t = tw; t < t0; t++) {
        float xv = buf[t & 15];
        buf[t & 15] = yp[(size_t)(t + 16) * ROWSTRIDE];   // t+16 <= t0+15 < tend
        float yn = fmaf(xv, sc, sh);
        v = 0.5f * (v + yn);
        v = (v >= 1.f) ? 0.f : v;
    }
    if (write_rate) {
#pragma unroll 16
        for (int t = t0; t < tend; t++) {
            float xv = buf[t & 15];
            if (t + 16 < tend) buf[t & 15] = yp[(size_t)(t + 16) * ROWSTRIDE];
            float yn = fmaf(xv, sc, sh);
            v = 0.5f * (v + yn);
            float s = (v >= 1.f) ? 1.f : 0.f;
            cnt += s;
            v = (v >= 1.f) ? 0.f : v;
        }
        g_psum[chunk * 16384 + b * 256 + e] = cnt;   // partial counts (exact ints)
    } else {
#pragma unroll 16
        for (int t = t0; t < tend; t++) {
            float xv = buf[t & 15];
            if (t + 16 < tend) buf[t & 15] = yp[(size_t)(t + 16) * ROWSTRIDE];
            float yn = fmaf(xv, sc, sh);
            v = 0.5f * (v + yn);
            float s = (v >= 1.f) ? 1.f : 0.f;
            sp[(size_t)t * ROWSTRIDE] = __float2half(s);
            v = (v >= 1.f) ? 0.f : v;
        }
    }
}

// ---------------- head: combine chunk partial counts + linear --------------------
__global__ void head_k(const float* __restrict__ hw, const float* __restrict__ hb,
                       float* __restrict__ out) {
    __shared__ float rs[EE];
    int b = blockIdx.x, tid = threadIdx.x;   // 64 threads
    for (int j = tid; j < EE; j += 64) {
        float c = g_psum[0 * 16384 + b * 256 + j] + g_psum[1 * 16384 + b * 256 + j]
                + g_psum[2 * 16384 + b * 256 + j] + g_psum[3 * 16384 + b * 256 + j];
        rs[j] = c * (1.f / TT);
    }
    __syncthreads();
    if (tid < OUTD) {
        float acc = hb[tid];
#pragma unroll 8
        for (int e2 = 0; e2 < EE; e2++) acc += rs[e2] * hw[tid * EE + e2];
        out[b * OUTD + tid] = acc;
    }
}

// ---------------- launch ---------------------------------------------------------
extern "C" void kernel_launch(void* const* d_in, const int* in_sizes, int n_in,
                              void* d_out, int out_size) {
    const float *x = 0, *conv0_w = 0, *conv0_b = 0, *convs_w = 0, *convs_b = 0;
    const float *gamma = 0, *beta = 0, *head_w = 0, *head_b = 0;
    int n1024_seen = 0;
    int alphabetical = (n_in > 0 && in_sizes[0] == 1024);
    for (int i = 0; i < n_in; i++) {
        const float* p = (const float*)d_in[i];
        switch (in_sizes[i]) {
            case 524288: x = p; break;
            case 6144:   conv0_w = p; break;
            case 256:    conv0_b = p; break;
            case 589824: convs_w = p; break;
            case 768:    convs_b = p; break;
            case 16128:  head_w = p; break;
            case 63:     head_b = p; break;
            case 1024:
                if (n1024_seen == 0) { if (alphabetical) beta = p; else gamma = p; }
                else                 { if (alphabetical) gamma = p; else beta = p; }
                n1024_seen++;
                break;
            default: break;
        }
    }
    float* out = (float*)d_out;

    cudaFuncSetAttribute(conv_mma_k, cudaFuncAttributeMaxDynamicSharedMemorySize, SMEM_BYTES);

    prep_k<<<(2 * ROWSTRIDE + 255) / 256, 256>>>(conv0_w);
    conv0_k<<<TT, 256>>>(x, conv0_b);
    stats2_k<<<256, 128>>>(1024);
    lif_k<<<1024, 64>>>(gamma + 0 * EE, beta + 0 * EE, 0);

    repack_wh_k<<<(3 * 768 * 256 + 255) / 256, 256>>>(convs_w);

    for (int i = 0; i < 3; i++) {
        conv_mma_k<<<dim3(2, 512), 512, SMEM_BYTES>>>(i, convs_b + i * EE);
        stats2_k<<<256, 128>>>(512);
        lif_k<<<1024, 64>>>(gamma + (i + 1) * EE, beta + (i + 1) * EE, (i == 2) ? 1 : 0);
    }

    head_k<<<BB, 64>>>(head_w, head_b, out);
}

// round 15
// speedup vs baseline: 5.8784x; 1.0222x over previous
#include <cuda_runtime.h>
#include <cuda_fp16.h>
#include <cstdint>

#define BB 64
#define TT 1024
#define EE 256
#define CIN 8
#define OUTD 63
#define NROW (BB*TT)          // 65536
#define ROWSTRIDE (BB*EE)     // 16384
#define LIF_WARM 160

#define LO_SCALE 4096.f
#define LO_INV   (1.f/4096.f)

// ---------------- scratch ----------------------------------------------------
__device__ float g_y[NROW * EE];                                // conv out [(t*B+b)][e]
__device__ __align__(16) __half g_spad[(TT + 2) * ROWSTRIDE];   // fp16 spikes, t-padded
__device__ __align__(16) __half g_wh[3 * 2 * 768 * 256];        // fp16 weights [layer][split][k][n]
__device__ float g_w0[3 * CIN * EE];
__device__ float g_psum[EE * 1024];                             // [e][row]; also lif partial counts
__device__ float g_psq[EE * 1024];
__device__ float g_sum[EE];
__device__ float g_sq[EE];

// ---------------- ptx helpers ------------------------------------------------
__device__ __forceinline__ uint32_t smem_u32(const void* p) {
    uint32_t a;
    asm("{ .reg .u64 t; cvta.to.shared.u64 t, %1; cvt.u32.u64 %0, t; }" : "=r"(a) : "l"(p));
    return a;
}
__device__ __forceinline__ void ldm4(uint32_t* r, uint32_t a) {
    asm volatile("ldmatrix.sync.aligned.m8n8.x4.shared.b16 {%0,%1,%2,%3}, [%4];"
                 : "=r"(r[0]), "=r"(r[1]), "=r"(r[2]), "=r"(r[3]) : "r"(a));
}
__device__ __forceinline__ void ldm4t(uint32_t* r, uint32_t a) {
    asm volatile("ldmatrix.sync.aligned.m8n8.x4.trans.shared.b16 {%0,%1,%2,%3}, [%4];"
                 : "=r"(r[0]), "=r"(r[1]), "=r"(r[2]), "=r"(r[3]) : "r"(a));
}
__device__ __forceinline__ void mma_h(float* d, const uint32_t* a, const uint32_t* b) {
    asm volatile("mma.sync.aligned.m16n8k16.row.col.f32.f16.f16.f32 "
                 "{%0,%1,%2,%3}, {%4,%5,%6,%7}, {%8,%9}, {%0,%1,%2,%3};"
                 : "+f"(d[0]), "+f"(d[1]), "+f"(d[2]), "+f"(d[3])
                 : "r"(a[0]), "r"(a[1]), "r"(a[2]), "r"(a[3]), "r"(b[0]), "r"(b[1]));
}
__device__ __forceinline__ void cpa16(uint32_t dst, const void* src) {
    asm volatile("cp.async.cg.shared.global [%0], [%1], 16;" :: "r"(dst), "l"(src));
}
#define CPA_COMMIT() asm volatile("cp.async.commit_group;" ::: "memory")
#define CPA_WAIT1()  asm volatile("cp.async.wait_group 1;" ::: "memory")

// ---------------- prep kernels -----------------------------------------------
__global__ void repack_wh_k(const float* __restrict__ w) {
    int idx = blockIdx.x * blockDim.x + threadIdx.x;     // 3*768*256
    if (idx >= 3 * 768 * 256) return;
    int n = idx & 255;
    int k = (idx >> 8) % 768;          // k = kpos*256 + c
    int i = idx / (768 * 256);
    int kpos = k >> 8;
    int c = k & 255;
    float wf = w[((i * 256 + n) * 256 + c) * 3 + kpos];
    __half h0 = __float2half_rn(wf);
    float lo = (wf - __half2float(h0)) * LO_SCALE;
    __half h1 = __float2half_rn(lo);
    g_wh[((size_t)(i * 2 + 0) * 768 + k) * 256 + n] = h0;
    g_wh[((size_t)(i * 2 + 1) * 768 + k) * 256 + n] = h1;
}

// merged: conv0 weight repack + spad time-pad zeroing
__global__ void prep_k(const float* __restrict__ w0) {
    int idx = blockIdx.x * blockDim.x + threadIdx.x;
    if (idx < ROWSTRIDE) g_spad[idx] = __float2half(0.f);
    else if (idx < 2 * ROWSTRIDE) g_spad[(TT + 1) * ROWSTRIDE + (idx - ROWSTRIDE)] = __float2half(0.f);
    if (idx < 3 * CIN * 256) {
        int o = idx & 255;
        int c = (idx >> 8) & 7;
        int k = idx >> 11;
        g_w0[idx] = w0[(o * CIN + c) * 3 + k];
    }
}

// ---------------- conv0: one CTA per t, weights in regs, fused stats -----------
__global__ void __launch_bounds__(256) conv0_k(const float* __restrict__ x,
                                               const float* __restrict__ bias) {
    __shared__ float xs[64][24];
    int t = blockIdx.x;
    int tid = threadIdx.x;
    float wr[24];
#pragma unroll
    for (int j = 0; j < 24; j++) wr[j] = g_w0[j * 256 + tid];
    for (int q = tid; q < 64 * 24; q += 256) {
        int bl = q / 24, rem = q % 24;
        int k = rem >> 3, c = rem & 7;
        int ttm = t - 1 + k;
        float v = 0.f;
        if (ttm >= 0 && ttm < TT) v = x[((bl) * TT + ttm) * CIN + c];
        xs[bl][rem] = v;
    }
    __syncthreads();
    float bo = bias[tid];
    float s = 0.f, qq = 0.f;
#pragma unroll 2
    for (int r = 0; r < 64; r++) {
        float acc = bo;
#pragma unroll
        for (int j = 0; j < 24; j++) acc += wr[j] * xs[r][j];
        g_y[(size_t)(t * BB + r) * EE + tid] = acc;
        s += acc;
        qq += acc * acc;
    }
    g_psum[(size_t)tid * 1024 + t] = s;
    g_psq[(size_t)tid * 1024 + t] = qq;
}

// ---------------- fp16 scaled-2-split MMA conv GEMM (512 thr, K-chunk 64, 3-stage)
// CTA tile 128m x 128n; 16 warps, each 32x32. K = 768 x 2 splits, chunks of 64.
#define APITCH 72                       // 64 data halves + 8 pad
#define BPITCH 136                      // 128 data halves + 8 pad
#define A_H 9216                        // halves: A tile per stage (128*72)
#define B_SP 8704                       // halves: one split B tile (64*136)
#define ST_H (A_H + 2 * B_SP)           // 26624 halves per stage
#define NSTAGE 3
#define SMEM_HALVES (NSTAGE * ST_H)     // 79872
#define SMEM_BYTES (SMEM_HALVES * 2)    // 159744

__global__ void __launch_bounds__(512, 1) conv_mma_k(int layer, const float* __restrict__ bias) {
    extern __shared__ __half sm[];
    const int tid = threadIdx.x;
    const int lane = tid & 31;
    const int wid = tid >> 5;
    const int wm = wid & 3;
    const int wn = wid >> 2;
    const int mt = blockIdx.y;
    const int nb = blockIdx.x;

    const uint4* __restrict__ wsrc = (const uint4*)(g_wh + (size_t)layer * 2 * 768 * 256);

    float acch[2][4][4], accl[2][4][4];
#pragma unroll
    for (int mi = 0; mi < 2; mi++)
#pragma unroll
        for (int u = 0; u < 4; u++)
#pragma unroll
            for (int q = 0; q < 4; q++) { acch[mi][u][q] = 0.f; accl[mi][u][q] = 0.f; }

    const uint32_t smb = smem_u32(sm);

    // issue one 64-wide K chunk into stage st. chunk ck in 0..11.
    auto issue = [&](int ck, int st) {
        int kpos = ck >> 2, c0 = (ck & 3) << 6;
        uint32_t base = smb + (uint32_t)(st * ST_H) * 2;
        // A: 1024 x 16B, 2 per thread
#pragma unroll
        for (int it = 0; it < 2; it++) {
            int u = tid + it * 512;
            int row = u >> 3, jg = u & 7;
            cpa16(base + (row * APITCH + jg * 8) * 2,
                  g_spad + (size_t)(2 * mt + (row >> 6) + kpos) * ROWSTRIDE
                         + (row & 63) * 256 + c0 + jg * 8);
        }
        // B: 2048 x 16B, 4 per thread
#pragma unroll
        for (int it = 0; it < 4; it++) {
            int u = tid + it * 512;
            int s = u >> 10, rest = u & 1023;
            int kk = rest >> 4, g = rest & 15;
            cpa16(base + (A_H + s * B_SP + kk * BPITCH + g * 8) * 2,
                  wsrc + (size_t)(s * 768 + kpos * 256 + c0 + kk) * 32 + nb * 16 + g);
        }
    };

#pragma unroll
    for (int p = 0; p < 2; p++) { issue(p, p); CPA_COMMIT(); }

    int st = 0;
    for (int ck = 0; ck < 12; ck++) {
        CPA_WAIT1();
        __syncthreads();
        if (ck + 2 < 12) {
            int st2 = st + 2; if (st2 >= 3) st2 -= 3;
            issue(ck + 2, st2);
        }
        CPA_COMMIT();

        const __half* Asm = sm + st * ST_H;
        const __half* Bsm = Asm + A_H;
#pragma unroll
        for (int kh = 0; kh < 4; kh++) {
            uint32_t afr[2][4];
#pragma unroll
            for (int mi = 0; mi < 2; mi++) {
                uint32_t ad = smem_u32(Asm + (wm * 32 + mi * 16 + (lane & 15)) * APITCH
                                       + kh * 16 + (lane >> 4) * 8);
                ldm4(afr[mi], ad);
            }
#pragma unroll
            for (int s = 0; s < 2; s++) {
                uint32_t bfr[2][4];
#pragma unroll
                for (int q = 0; q < 2; q++) {
                    uint32_t bd = smem_u32(Bsm + s * B_SP + (kh * 16 + (lane & 15)) * BPITCH
                                           + wn * 32 + q * 16 + (lane >> 4) * 8);
                    ldm4t(bfr[q], bd);
                }
                if (s == 0) {
#pragma unroll
                    for (int mi = 0; mi < 2; mi++)
#pragma unroll
                        for (int q = 0; q < 2; q++)
#pragma unroll
                            for (int h = 0; h < 2; h++)
                                mma_h(acch[mi][q * 2 + h], afr[mi], &bfr[q][h * 2]);
                } else {
#pragma unroll
                    for (int mi = 0; mi < 2; mi++)
#pragma unroll
                        for (int q = 0; q < 2; q++)
#pragma unroll
                            for (int h = 0; h < 2; h++)
                                mma_h(accl[mi][q * 2 + h], afr[mi], &bfr[q][h * 2]);
                }
            }
        }
        if (++st >= 3) st -= 3;
    }

    // epilogue: combine splits, write y, fused column stats
    __syncthreads();
    float* red = (float*)sm;

    const int m0 = mt * 128 + wm * 32 + (lane >> 2);
    float csum[8], csq[8];
#pragma unroll
    for (int j = 0; j < 8; j++) { csum[j] = 0.f; csq[j] = 0.f; }

#pragma unroll
    for (int u = 0; u < 4; u++) {
        int n = nb * 128 + wn * 32 + (u >> 1) * 16 + (u & 1) * 8 + (lane & 3) * 2;
        float2 bv = *(const float2*)(bias + n);
#pragma unroll
        for (int mi = 0; mi < 2; mi++) {
            int r0 = m0 + mi * 16;
            float v00 = fmaf(accl[mi][u][0], LO_INV, acch[mi][u][0]) + bv.x;
            float v01 = fmaf(accl[mi][u][1], LO_INV, acch[mi][u][1]) + bv.y;
            float v10 = fmaf(accl[mi][u][2], LO_INV, acch[mi][u][2]) + bv.x;
            float v11 = fmaf(accl[mi][u][3], LO_INV, acch[mi][u][3]) + bv.y;
            float2 w0, w1;
            w0.x = v00; w0.y = v01;
            w1.x = v10; w1.y = v11;
            *(float2*)(g_y + (size_t)r0 * 256 + n) = w0;
            *(float2*)(g_y + (size_t)(r0 + 8) * 256 + n) = w1;
            csum[u * 2 + 0] += v00 + v10;
            csum[u * 2 + 1] += v01 + v11;
            csq[u * 2 + 0] += v00 * v00 + v10 * v10;
            csq[u * 2 + 1] += v01 * v01 + v11 * v11;
        }
    }
#pragma unroll
    for (int off = 4; off < 32; off <<= 1)
#pragma unroll
        for (int j = 0; j < 8; j++) {
            csum[j] += __shfl_xor_sync(0xffffffffu, csum[j], off);
            csq[j]  += __shfl_xor_sync(0xffffffffu, csq[j],  off);
        }
    if (lane < 4) {
#pragma unroll
        for (int j = 0; j < 8; j++) {
            int u = j >> 1;
            int cl = wn * 32 + (u >> 1) * 16 + (u & 1) * 8 + lane * 2 + (j & 1);
            red[wm * 128 + cl] = csum[j];
            red[512 + wm * 128 + cl] = csq[j];
        }
    }
    __syncthreads();
    if (tid < 128) {
        float s = red[tid] + red[128 + tid] + red[256 + tid] + red[384 + tid];
        float q = red[512 + tid] + red[640 + tid] + red[768 + tid] + red[896 + tid];
        g_psum[(size_t)(nb * 128 + tid) * 1024 + mt] = s;
        g_psq[(size_t)(nb * 128 + tid) * 1024 + mt] = q;
    }
}

// ---------------- BN stats finalize: 1 block per channel ------------------------
__global__ void __launch_bounds__(128) stats2_k(int nrows) {
    __shared__ float ss[128], qq[128];
    int e = blockIdx.x;
    int t = threadIdx.x;
    const float* ps = g_psum + (size_t)e * 1024;
    const float* pq = g_psq + (size_t)e * 1024;
    float s = 0.f, q = 0.f;
    for (int r = t; r < nrows; r += 128) { s += ps[r]; q += pq[r]; }
    ss[t] = s; qq[t] = q;
    __syncthreads();
#pragma unroll
    for (int off = 64; off > 0; off >>= 1) {
        if (t < off) { ss[t] += ss[t + off]; qq[t] += qq[t + off]; }
        __syncthreads();
    }
    if (t == 0) { g_sum[e] = ss[0]; g_sq[e] = qq[0]; }
}

// ---------------- BN apply + LIF, time-chunked with warmup collapse -------------
// grid = 4 chunks x 64 b x 4 e-quarters = 1024 blocks x 64 threads.
__global__ void __launch_bounds__(64) lif_k(const float* __restrict__ gamma,
                                            const float* __restrict__ beta,
                                            int write_rate) {
    int blk = blockIdx.x;
    int chunk = blk >> 8;                      // 0..3
    int r = blk & 255;
    int b = r >> 2;
    int e = ((r & 3) << 6) + threadIdx.x;
    float mu = g_sum[e] * (1.f / NROW);
    float var = g_sq[e] * (1.f / NROW) - mu * mu;
    float sc = gamma[e] / sqrtf(var + 1e-5f);
    float sh = fmaf(-mu, sc, beta[e]);

    const int t0 = chunk << 8;
    const int tw = (chunk == 0) ? 0 : (t0 - LIF_WARM);
    const int tend = t0 + 256;
    const float* yp = g_y + b * 256 + e;
    __half* sp = g_spad + (size_t)ROWSTRIDE + b * 256 + e;

    float buf[16];
#pragma unroll
    for (int i = 0; i < 16; i++) buf[i] = yp[(size_t)(tw + i) * ROWSTRIDE];
    float v = 0.f, cnt = 0.f;

#pragma unroll 16
    for (int t = tw; t < t0; t++) {
        float xv = buf[t & 15];
        buf[t & 15] = yp[(size_t)(t + 16) * ROWSTRIDE];
        float yn = fmaf(xv, sc, sh);
        v = 0.5f * (v + yn);
        v = (v >= 1.f) ? 0.f : v;
    }
    if (write_rate) {
#pragma unroll 16
        for (int t = t0; t < tend; t++) {
            float xv = buf[t & 15];
            if (t + 16 < tend) buf[t & 15] = yp[(size_t)(t + 16) * ROWSTRIDE];
            float yn = fmaf(xv, sc, sh);
            v = 0.5f * (v + yn);
            float s = (v >= 1.f) ? 1.f : 0.f;
            cnt += s;
            v = (v >= 1.f) ? 0.f : v;
        }
        g_psum[chunk * 16384 + b * 256 + e] = cnt;   // partial counts (exact ints)
    } else {
#pragma unroll 16
        for (int t = t0; t < tend; t++) {
            float xv = buf[t & 15];
            if (t + 16 < tend) buf[t & 15] = yp[(size_t)(t + 16) * ROWSTRIDE];
            float yn = fmaf(xv, sc, sh);
            v = 0.5f * (v + yn);
            float s = (v >= 1.f) ? 1.f : 0.f;
            sp[(size_t)t * ROWSTRIDE] = __float2half(s);
            v = (v >= 1.f) ? 0.f : v;
        }
    }
}

// ---------------- head: combine chunk partial counts + linear --------------------
__global__ void head_k(const float* __restrict__ hw, const float* __restrict__ hb,
                       float* __restrict__ out) {
    __shared__ float rs[EE];
    int b = blockIdx.x, tid = threadIdx.x;   // 64 threads
    for (int j = tid; j < EE; j += 64) {
        float c = g_psum[0 * 16384 + b * 256 + j] + g_psum[1 * 16384 + b * 256 + j]
                + g_psum[2 * 16384 + b * 256 + j] + g_psum[3 * 16384 + b * 256 + j];
        rs[j] = c * (1.f / TT);
    }
    __syncthreads();
    if (tid < OUTD) {
        float acc = hb[tid];
#pragma unroll 8
        for (int e2 = 0; e2 < EE; e2++) acc += rs[e2] * hw[tid * EE + e2];
        out[b * OUTD + tid] = acc;
    }
}

// ---------------- launch ---------------------------------------------------------
extern "C" void kernel_launch(void* const* d_in, const int* in_sizes, int n_in,
                              void* d_out, int out_size) {
    const float *x = 0, *conv0_w = 0, *conv0_b = 0, *convs_w = 0, *convs_b = 0;
    const float *gamma = 0, *beta = 0, *head_w = 0, *head_b = 0;
    int n1024_seen = 0;
    int alphabetical = (n_in > 0 && in_sizes[0] == 1024);
    for (int i = 0; i < n_in; i++) {
        const float* p = (const float*)d_in[i];
        switch (in_sizes[i]) {
            case 524288: x = p; break;
            case 6144:   conv0_w = p; break;
            case 256:    conv0_b = p; break;
            case 589824: convs_w = p; break;
            case 768:    convs_b = p; break;
            case 16128:  head_w = p; break;
            case 63:     head_b = p; break;
            case 1024:
                if (n1024_seen == 0) { if (alphabetical) beta = p; else gamma = p; }
                else                 { if (alphabetical) gamma = p; else beta = p; }
                n1024_seen++;
                break;
            default: break;
        }
    }
    float* out = (float*)d_out;

    cudaFuncSetAttribute(conv_mma_k, cudaFuncAttributeMaxDynamicSharedMemorySize, SMEM_BYTES);

    prep_k<<<(2 * ROWSTRIDE + 255) / 256, 256>>>(conv0_w);
    conv0_k<<<TT, 256>>>(x, conv0_b);
    stats2_k<<<256, 128>>>(1024);
    lif_k<<<1024, 64>>>(gamma + 0 * EE, beta + 0 * EE, 0);

    repack_wh_k<<<(3 * 768 * 256 + 255) / 256, 256>>>(convs_w);

    for (int i = 0; i < 3; i++) {
        conv_mma_k<<<dim3(2, 512), 512, SMEM_BYTES>>>(i, convs_b + i * EE);
        stats2_k<<<256, 128>>>(512);
        lif_k<<<1024, 64>>>(gamma + (i + 1) * EE, beta + (i + 1) * EE, (i == 2) ? 1 : 0);
    }

    head_k<<<BB, 64>>>(head_w, head_b, out);
}

// round 16
// speedup vs baseline: 6.0766x; 1.0337x over previous
#include <cuda_runtime.h>
#include <cuda_fp16.h>
#include <cstdint>

#define BB 64
#define TT 1024
#define EE 256
#define CIN 8
#define OUTD 63
#define NROW (BB*TT)          // 65536
#define ROWSTRIDE (BB*EE)     // 16384
#define LIF_WARM 160

#define LO_SCALE 4096.f
#define LO_INV   (1.f/4096.f)

// ---------------- scratch ----------------------------------------------------
__device__ float g_y[NROW * EE];                                // conv out [(t*B+b)][e]
__device__ __align__(16) __half g_spad[(TT + 2) * ROWSTRIDE];   // fp16 spikes, t-padded
__device__ __align__(16) __half g_wh[3 * 2 * 768 * 256];        // fp16 weights [layer][split][k][n]
__device__ float g_w0[3 * CIN * EE];
__device__ float g_psum[EE * 1024];                             // [e][row]; also lif partial counts
__device__ float g_psq[EE * 1024];
__device__ float g_sum[EE];
__device__ float g_sq[EE];

// ---------------- ptx helpers ------------------------------------------------
__device__ __forceinline__ uint32_t smem_u32(const void* p) {
    uint32_t a;
    asm("{ .reg .u64 t; cvta.to.shared.u64 t, %1; cvt.u32.u64 %0, t; }" : "=r"(a) : "l"(p));
    return a;
}
__device__ __forceinline__ void ldm4(uint32_t* r, uint32_t a) {
    asm volatile("ldmatrix.sync.aligned.m8n8.x4.shared.b16 {%0,%1,%2,%3}, [%4];"
                 : "=r"(r[0]), "=r"(r[1]), "=r"(r[2]), "=r"(r[3]) : "r"(a));
}
__device__ __forceinline__ void ldm4t(uint32_t* r, uint32_t a) {
    asm volatile("ldmatrix.sync.aligned.m8n8.x4.trans.shared.b16 {%0,%1,%2,%3}, [%4];"
                 : "=r"(r[0]), "=r"(r[1]), "=r"(r[2]), "=r"(r[3]) : "r"(a));
}
__device__ __forceinline__ void mma_h(float* d, const uint32_t* a, const uint32_t* b) {
    asm volatile("mma.sync.aligned.m16n8k16.row.col.f32.f16.f16.f32 "
                 "{%0,%1,%2,%3}, {%4,%5,%6,%7}, {%8,%9}, {%0,%1,%2,%3};"
                 : "+f"(d[0]), "+f"(d[1]), "+f"(d[2]), "+f"(d[3])
                 : "r"(a[0]), "r"(a[1]), "r"(a[2]), "r"(a[3]), "r"(b[0]), "r"(b[1]));
}
__device__ __forceinline__ void cpa16(uint32_t dst, const void* src) {
    asm volatile("cp.async.cg.shared.global [%0], [%1], 16;" :: "r"(dst), "l"(src));
}
#define CPA_COMMIT() asm volatile("cp.async.commit_group;" ::: "memory")
#define CPA_WAIT1()  asm volatile("cp.async.wait_group 1;" ::: "memory")

// ---------------- prep kernels -----------------------------------------------
__global__ void repack_wh_k(const float* __restrict__ w) {
    int idx = blockIdx.x * blockDim.x + threadIdx.x;     // 3*768*256
    if (idx >= 3 * 768 * 256) return;
    int n = idx & 255;
    int k = (idx >> 8) % 768;          // k = kpos*256 + c
    int i = idx / (768 * 256);
    int kpos = k >> 8;
    int c = k & 255;
    float wf = w[((i * 256 + n) * 256 + c) * 3 + kpos];
    __half h0 = __float2half_rn(wf);
    float lo = (wf - __half2float(h0)) * LO_SCALE;
    __half h1 = __float2half_rn(lo);
    g_wh[((size_t)(i * 2 + 0) * 768 + k) * 256 + n] = h0;
    g_wh[((size_t)(i * 2 + 1) * 768 + k) * 256 + n] = h1;
}

// merged: conv0 weight repack + spad time-pad zeroing
__global__ void prep_k(const float* __restrict__ w0) {
    int idx = blockIdx.x * blockDim.x + threadIdx.x;
    if (idx < ROWSTRIDE) g_spad[idx] = __float2half(0.f);
    else if (idx < 2 * ROWSTRIDE) g_spad[(TT + 1) * ROWSTRIDE + (idx - ROWSTRIDE)] = __float2half(0.f);
    if (idx < 3 * CIN * 256) {
        int o = idx & 255;
        int c = (idx >> 8) & 7;
        int k = idx >> 11;
        g_w0[idx] = w0[(o * CIN + c) * 3 + k];
    }
}

// ---------------- conv0: one CTA per t, weights in regs, fused stats -----------
__global__ void __launch_bounds__(256) conv0_k(const float* __restrict__ x,
                                               const float* __restrict__ bias) {
    __shared__ float xs[64][24];
    int t = blockIdx.x;
    int tid = threadIdx.x;
    float wr[24];
#pragma unroll
    for (int j = 0; j < 24; j++) wr[j] = g_w0[j * 256 + tid];
    for (int q = tid; q < 64 * 24; q += 256) {
        int bl = q / 24, rem = q % 24;
        int k = rem >> 3, c = rem & 7;
        int ttm = t - 1 + k;
        float v = 0.f;
        if (ttm >= 0 && ttm < TT) v = x[((bl) * TT + ttm) * CIN + c];
        xs[bl][rem] = v;
    }
    __syncthreads();
    float bo = bias[tid];
    float s = 0.f, qq = 0.f;
#pragma unroll 2
    for (int r = 0; r < 64; r++) {
        float acc = bo;
#pragma unroll
        for (int j = 0; j < 24; j++) acc += wr[j] * xs[r][j];
        g_y[(size_t)(t * BB + r) * EE + tid] = acc;
        s += acc;
        qq += acc * acc;
    }
    g_psum[(size_t)tid * 1024 + t] = s;
    g_psq[(size_t)tid * 1024 + t] = qq;
}

// ---------------- fp16 scaled-2-split MMA conv GEMM ------------------------------
// CTA tile 128m x 64n, 256 thr (8 warps, 32x32 each), K-chunk 32, 3-stage, 2 CTA/SM.
#define APITCH 40                       // 32 data halves + 8 pad
#define BPITCH 72                       // 64 data halves + 8 pad
#define A_H 5120                        // halves: A tile per stage (128*40)
#define B_SP 2304                       // halves: one split B tile (32*72)
#define ST_H (A_H + 2 * B_SP)           // 9728 halves per stage
#define NSTAGE 3
#define SMEM_HALVES (NSTAGE * ST_H)     // 29184
#define SMEM_BYTES (SMEM_HALVES * 2)    // 58368

__global__ void __launch_bounds__(256, 2) conv_mma_k(int layer, const float* __restrict__ bias) {
    extern __shared__ __half sm[];
    const int tid = threadIdx.x;
    const int lane = tid & 31;
    const int wid = tid >> 5;
    const int wm = wid & 3;          // warp M group (32 rows)
    const int wn = wid >> 2;         // warp N group (0..1, 32 cols)
    const int mt = blockIdx.y;       // 512 M tiles
    const int nb = blockIdx.x;       // 4 N tiles of 64

    const uint4* __restrict__ wsrc = (const uint4*)(g_wh + (size_t)layer * 2 * 768 * 256);

    float acch[2][4][4], accl[2][4][4];
#pragma unroll
    for (int mi = 0; mi < 2; mi++)
#pragma unroll
        for (int u = 0; u < 4; u++)
#pragma unroll
            for (int q = 0; q < 4; q++) { acch[mi][u][q] = 0.f; accl[mi][u][q] = 0.f; }

    const uint32_t smb = smem_u32(sm);

    // one 32-wide K chunk into stage st; ck in 0..23
    auto issue = [&](int ck, int st) {
        int kpos = ck >> 3, c0 = (ck & 7) << 5;
        uint32_t base = smb + (uint32_t)(st * ST_H) * 2;
        // A: 512 x 16B (128 rows x 4 granules), 2 per thread
#pragma unroll
        for (int it = 0; it < 2; it++) {
            int u = tid + it * 256;
            int row = u >> 2, jg = u & 3;
            cpa16(base + (row * APITCH + jg * 8) * 2,
                  g_spad + (size_t)(2 * mt + (row >> 6) + kpos) * ROWSTRIDE
                         + (row & 63) * 256 + c0 + jg * 8);
        }
        // B: 512 x 16B (2 splits x 32 k x 8 granules of 64 cols), 2 per thread
#pragma unroll
        for (int it = 0; it < 2; it++) {
            int u = tid + it * 256;
            int s = u >> 8, rest = u & 255;
            int kk = rest >> 3, g = rest & 7;
            cpa16(base + (A_H + s * B_SP + kk * BPITCH + g * 8) * 2,
                  wsrc + (size_t)(s * 768 + kpos * 256 + c0 + kk) * 32 + nb * 8 + g);
        }
    };

#pragma unroll
    for (int p = 0; p < 2; p++) { issue(p, p); CPA_COMMIT(); }

    int st = 0;
    for (int ck = 0; ck < 24; ck++) {
        CPA_WAIT1();
        __syncthreads();
        if (ck + 2 < 24) {
            int st2 = st + 2; if (st2 >= 3) st2 -= 3;
            issue(ck + 2, st2);
        }
        CPA_COMMIT();

        const __half* Asm = sm + st * ST_H;
        const __half* Bsm = Asm + A_H;
#pragma unroll
        for (int kh = 0; kh < 2; kh++) {
            uint32_t afr[2][4];
#pragma unroll
            for (int mi = 0; mi < 2; mi++) {
                uint32_t ad = smem_u32(Asm + (wm * 32 + mi * 16 + (lane & 15)) * APITCH
                                       + kh * 16 + (lane >> 4) * 8);
                ldm4(afr[mi], ad);
            }
#pragma unroll
            for (int s = 0; s < 2; s++) {
                uint32_t bfr[2][4];
#pragma unroll
                for (int q = 0; q < 2; q++) {
                    uint32_t bd = smem_u32(Bsm + s * B_SP + (kh * 16 + (lane & 15)) * BPITCH
                                           + wn * 32 + q * 16 + (lane >> 4) * 8);
                    ldm4t(bfr[q], bd);
                }
                if (s == 0) {
#pragma unroll
                    for (int mi = 0; mi < 2; mi++)
#pragma unroll
                        for (int q = 0; q < 2; q++)
#pragma unroll
                            for (int h = 0; h < 2; h++)
                                mma_h(acch[mi][q * 2 + h], afr[mi], &bfr[q][h * 2]);
                } else {
#pragma unroll
                    for (int mi = 0; mi < 2; mi++)
#pragma unroll
                        for (int q = 0; q < 2; q++)
#pragma unroll
                            for (int h = 0; h < 2; h++)
                                mma_h(accl[mi][q * 2 + h], afr[mi], &bfr[q][h * 2]);
                }
            }
        }
        if (++st >= 3) st -= 3;
    }

    // epilogue: combine splits, write y, fused column stats
    __syncthreads();
    float* red = (float*)sm;      // [wm][64] sums @0, sq @256

    const int m0 = mt * 128 + wm * 32 + (lane >> 2);
    float csum[8], csq[8];
#pragma unroll
    for (int j = 0; j < 8; j++) { csum[j] = 0.f; csq[j] = 0.f; }

#pragma unroll
    for (int u = 0; u < 4; u++) {
        int n = nb * 64 + wn * 32 + (u >> 1) * 16 + (u & 1) * 8 + (lane & 3) * 2;
        float2 bv = *(const float2*)(bias + n);
#pragma unroll
        for (int mi = 0; mi < 2; mi++) {
            int r0 = m0 + mi * 16;
            float v00 = fmaf(accl[mi][u][0], LO_INV, acch[mi][u][0]) + bv.x;
            float v01 = fmaf(accl[mi][u][1], LO_INV, acch[mi][u][1]) + bv.y;
            float v10 = fmaf(accl[mi][u][2], LO_INV, acch[mi][u][2]) + bv.x;
            float v11 = fmaf(accl[mi][u][3], LO_INV, acch[mi][u][3]) + bv.y;
            float2 w0, w1;
            w0.x = v00; w0.y = v01;
            w1.x = v10; w1.y = v11;
            *(float2*)(g_y + (size_t)r0 * 256 + n) = w0;
            *(float2*)(g_y + (size_t)(r0 + 8) * 256 + n) = w1;
            csum[u * 2 + 0] += v00 + v10;
            csum[u * 2 + 1] += v01 + v11;
            csq[u * 2 + 0] += v00 * v00 + v10 * v10;
            csq[u * 2 + 1] += v01 * v01 + v11 * v11;
        }
    }
#pragma unroll
    for (int off = 4; off < 32; off <<= 1)
#pragma unroll
        for (int j = 0; j < 8; j++) {
            csum[j] += __shfl_xor_sync(0xffffffffu, csum[j], off);
            csq[j]  += __shfl_xor_sync(0xffffffffu, csq[j],  off);
        }
    if (lane < 4) {
#pragma unroll
        for (int j = 0; j < 8; j++) {
            int u = j >> 1;
            int cl = wn * 32 + (u >> 1) * 16 + (u & 1) * 8 + lane * 2 + (j & 1);  // 0..63
            red[wm * 64 + cl] = csum[j];
            red[256 + wm * 64 + cl] = csq[j];
        }
    }
    __syncthreads();
    if (tid < 64) {
        float s = red[tid] + red[64 + tid] + red[128 + tid] + red[192 + tid];
        float q = red[256 + tid] + red[320 + tid] + red[384 + tid] + red[448 + tid];
        g_psum[(size_t)(nb * 64 + tid) * 1024 + mt] = s;
        g_psq[(size_t)(nb * 64 + tid) * 1024 + mt] = q;
    }
}

// ---------------- BN stats finalize: 1 block per channel ------------------------
__global__ void __launch_bounds__(128) stats2_k(int nrows) {
    __shared__ float ss[128], qq[128];
    int e = blockIdx.x;
    int t = threadIdx.x;
    const float* ps = g_psum + (size_t)e * 1024;
    const float* pq = g_psq + (size_t)e * 1024;
    float s = 0.f, q = 0.f;
    for (int r = t; r < nrows; r += 128) { s += ps[r]; q += pq[r]; }
    ss[t] = s; qq[t] = q;
    __syncthreads();
#pragma unroll
    for (int off = 64; off > 0; off >>= 1) {
        if (t < off) { ss[t] += ss[t + off]; qq[t] += qq[t + off]; }
        __syncthreads();
    }
    if (t == 0) { g_sum[e] = ss[0]; g_sq[e] = qq[0]; }
}

// ---------------- BN apply + LIF, time-chunked with warmup collapse -------------
// grid = 4 chunks x 64 b x 4 e-quarters = 1024 blocks x 64 threads.
__global__ void __launch_bounds__(64) lif_k(const float* __restrict__ gamma,
                                            const float* __restrict__ beta,
                                            int write_rate) {
    int blk = blockIdx.x;
    int chunk = blk >> 8;                      // 0..3
    int r = blk & 255;
    int b = r >> 2;
    int e = ((r & 3) << 6) + threadIdx.x;
    float mu = g_sum[e] * (1.f / NROW);
    float var = g_sq[e] * (1.f / NROW) - mu * mu;
    float sc = gamma[e] / sqrtf(var + 1e-5f);
    float sh = fmaf(-mu, sc, beta[e]);

    const int t0 = chunk << 8;
    const int tw = (chunk == 0) ? 0 : (t0 - LIF_WARM);
    const int tend = t0 + 256;
    const float* yp = g_y + b * 256 + e;
    __half* sp = g_spad + (size_t)ROWSTRIDE + b * 256 + e;

    float buf[16];
#pragma unroll
    for (int i = 0; i < 16; i++) buf[i] = yp[(size_t)(tw + i) * ROWSTRIDE];
    float v = 0.f, cnt = 0.f;

#pragma unroll 16
    for (int t = tw; t < t0; t++) {
        float xv = buf[t & 15];
        buf[t & 15] = yp[(size_t)(t + 16) * ROWSTRIDE];
        float yn = fmaf(xv, sc, sh);
        v = 0.5f * (v + yn);
        v = (v >= 1.f) ? 0.f : v;
    }
    if (write_rate) {
#pragma unroll 16
        for (int t = t0; t < tend; t++) {
            float xv = buf[t & 15];
            if (t + 16 < tend) buf[t & 15] = yp[(size_t)(t + 16) * ROWSTRIDE];
            float yn = fmaf(xv, sc, sh);
            v = 0.5f * (v + yn);
            float s = (v >= 1.f) ? 1.f : 0.f;
            cnt += s;
            v = (v >= 1.f) ? 0.f : v;
        }
        g_psum[chunk * 16384 + b * 256 + e] = cnt;   // partial counts (exact ints)
    } else {
#pragma unroll 16
        for (int t = t0; t < tend; t++) {
            float xv = buf[t & 15];
            if (t + 16 < tend) buf[t & 15] = yp[(size_t)(t + 16) * ROWSTRIDE];
            float yn = fmaf(xv, sc, sh);
            v = 0.5f * (v + yn);
            float s = (v >= 1.f) ? 1.f : 0.f;
            sp[(size_t)t * ROWSTRIDE] = __float2half(s);
            v = (v >= 1.f) ? 0.f : v;
        }
    }
}

// ---------------- head: combine chunk partial counts + linear --------------------
__global__ void head_k(const float* __restrict__ hw, const float* __restrict__ hb,
                       float* __restrict__ out) {
    __shared__ float rs[EE];
    int b = blockIdx.x, tid = threadIdx.x;   // 64 threads
    for (int j = tid; j < EE; j += 64) {
        float c = g_psum[0 * 16384 + b * 256 + j] + g_psum[1 * 16384 + b * 256 + j]
                + g_psum[2 * 16384 + b * 256 + j] + g_psum[3 * 16384 + b * 256 + j];
        rs[j] = c * (1.f / TT);
    }
    __syncthreads();
    if (tid < OUTD) {
        float acc = hb[tid];
#pragma unroll 8
        for (int e2 = 0; e2 < EE; e2++) acc += rs[e2] * hw[tid * EE + e2];
        out[b * OUTD + tid] = acc;
    }
}

// ---------------- launch ---------------------------------------------------------
extern "C" void kernel_launch(void* const* d_in, const int* in_sizes, int n_in,
                              void* d_out, int out_size) {
    const float *x = 0, *conv0_w = 0, *conv0_b = 0, *convs_w = 0, *convs_b = 0;
    const float *gamma = 0, *beta = 0, *head_w = 0, *head_b = 0;
    int n1024_seen = 0;
    int alphabetical = (n_in > 0 && in_sizes[0] == 1024);
    for (int i = 0; i < n_in; i++) {
        const float* p = (const float*)d_in[i];
        switch (in_sizes[i]) {
            case 524288: x = p; break;
            case 6144:   conv0_w = p; break;
            case 256:    conv0_b = p; break;
            case 589824: convs_w = p; break;
            case 768:    convs_b = p; break;
            case 16128:  head_w = p; break;
            case 63:     head_b = p; break;
            case 1024:
                if (n1024_seen == 0) { if (alphabetical) beta = p; else gamma = p; }
                else                 { if (alphabetical) gamma = p; else beta = p; }
                n1024_seen++;
                break;
            default: break;
        }
    }
    float* out = (float*)d_out;

    cudaFuncSetAttribute(conv_mma_k, cudaFuncAttributeMaxDynamicSharedMemorySize, SMEM_BYTES);

    prep_k<<<(2 * ROWSTRIDE + 255) / 256, 256>>>(conv0_w);
    conv0_k<<<TT, 256>>>(x, conv0_b);
    stats2_k<<<256, 128>>>(1024);
    lif_k<<<1024, 64>>>(gamma + 0 * EE, beta + 0 * EE, 0);

    repack_wh_k<<<(3 * 768 * 256 + 255) / 256, 256>>>(convs_w);

    for (int i = 0; i < 3; i++) {
        conv_mma_k<<<dim3(4, 512), 256, SMEM_BYTES>>>(i, convs_b + i * EE);
        stats2_k<<<256, 128>>>(512);
        lif_k<<<1024, 64>>>(gamma + (i + 1) * EE, beta + (i + 1) * EE, (i == 2) ? 1 : 0);
    }

    head_k<<<BB, 64>>>(head_w, head_b, out);
}